// round 2
// baseline (speedup 1.0000x reference)
#include <cuda_runtime.h>
#include <math.h>

#define BATCH 8
#define NLAT  256
#define SEQ   4096
#define DIM   1024
#define HEADS 16
#define DHEAD 64
#define INNER 1024
#define EPSLN 1e-5f

// ---------------- scratch (device globals: no runtime allocation) ----------
__device__ float g_lat_n[BATCH * NLAT * DIM];                 //   8 MB
__device__ float g_ctx_n[(size_t)BATCH * SEQ * DIM];          // 128 MB
__device__ float g_q[BATCH * NLAT * INNER];                   //   8 MB
__device__ float g_kv[(size_t)BATCH * SEQ * 2 * INNER];       // 256 MB (k | v)
__device__ float g_attn[BATCH * NLAT * INNER];                //   8 MB

// ---------------- LayerNorm: one block per row of 1024 ---------------------
__global__ __launch_bounds__(256) void ln_kernel(
    const float* __restrict__ x, const float* __restrict__ gam,
    const float* __restrict__ bet, float* __restrict__ y)
{
    const int row = blockIdx.x;
    const int t = threadIdx.x;
    __shared__ float red[8];

    const float4 v = ((const float4*)(x + (size_t)row * DIM))[t];

    // mean
    float s = v.x + v.y + v.z + v.w;
    #pragma unroll
    for (int off = 16; off; off >>= 1) s += __shfl_xor_sync(0xffffffffu, s, off);
    if ((t & 31) == 0) red[t >> 5] = s;
    __syncthreads();
    if (t < 8) {
        float r = red[t];
        #pragma unroll
        for (int off = 4; off; off >>= 1) r += __shfl_xor_sync(0xffu, r, off);
        if (t == 0) red[0] = r;
    }
    __syncthreads();
    const float mu = red[0] * (1.0f / DIM);

    const float dx = v.x - mu, dy = v.y - mu, dz = v.z - mu, dw = v.w - mu;
    float s2 = dx * dx + dy * dy + dz * dz + dw * dw;
    __syncthreads();   // everyone has consumed red[0]; safe to reuse
    #pragma unroll
    for (int off = 16; off; off >>= 1) s2 += __shfl_xor_sync(0xffffffffu, s2, off);
    if ((t & 31) == 0) red[t >> 5] = s2;
    __syncthreads();
    if (t < 8) {
        float r = red[t];
        #pragma unroll
        for (int off = 4; off; off >>= 1) r += __shfl_xor_sync(0xffu, r, off);
        if (t == 0) red[0] = r;
    }
    __syncthreads();
    const float rs = rsqrtf(red[0] * (1.0f / DIM) + EPSLN);

    const float4 gg = ((const float4*)gam)[t];
    const float4 bb = ((const float4*)bet)[t];
    float4 o;
    o.x = dx * rs * gg.x + bb.x;
    o.y = dy * rs * gg.y + bb.y;
    o.z = dz * rs * gg.z + bb.z;
    o.w = dw * rs * gg.w + bb.w;
    ((float4*)(y + (size_t)row * DIM))[t] = o;
}

// ---------------- SGEMM 128x128x8, 256 threads, 8x8 per thread -------------
template <bool BIAS>
__global__ __launch_bounds__(256) void sgemm128(
    const float* __restrict__ A, const float* __restrict__ Bm,
    const float* __restrict__ bias, float* __restrict__ C,
    int M, int N, int K)
{
    __shared__ float As[8][128];
    __shared__ float Bs[8][128];

    const int tid = threadIdx.x;
    const int tx = tid & 15, ty = tid >> 4;
    const int bx = blockIdx.x, by = blockIdx.y;

    const int arow = tid >> 1,  acol = (tid & 1) * 4;   // A tile 128x8 load
    const int brow = tid >> 5,  bcol = (tid & 31) * 4;  // B tile 8x128 load
    const float* Aptr = A + (size_t)(by * 128 + arow) * K + acol;
    const float* Bptr = Bm + (size_t)brow * N + bx * 128 + bcol;

    float acc[8][8];
    #pragma unroll
    for (int i = 0; i < 8; i++)
        #pragma unroll
        for (int j = 0; j < 8; j++) acc[i][j] = 0.f;

    for (int k0 = 0; k0 < K; k0 += 8) {
        const float4 av = *(const float4*)(Aptr + k0);
        const float4 bv = *(const float4*)(Bptr + (size_t)k0 * N);
        As[acol + 0][arow] = av.x;
        As[acol + 1][arow] = av.y;
        As[acol + 2][arow] = av.z;
        As[acol + 3][arow] = av.w;
        *(float4*)&Bs[brow][bcol] = bv;
        __syncthreads();

        #pragma unroll
        for (int kk = 0; kk < 8; kk++) {
            const float4 a0 = *(float4*)&As[kk][ty * 4];
            const float4 a1 = *(float4*)&As[kk][64 + ty * 4];
            const float4 b0 = *(float4*)&Bs[kk][tx * 4];
            const float4 b1 = *(float4*)&Bs[kk][64 + tx * 4];
            const float a[8] = {a0.x, a0.y, a0.z, a0.w, a1.x, a1.y, a1.z, a1.w};
            const float b[8] = {b0.x, b0.y, b0.z, b0.w, b1.x, b1.y, b1.z, b1.w};
            #pragma unroll
            for (int i = 0; i < 8; i++)
                #pragma unroll
                for (int j = 0; j < 8; j++) acc[i][j] += a[i] * b[j];
        }
        __syncthreads();
    }

    #pragma unroll
    for (int ih = 0; ih < 2; ih++)
        #pragma unroll
        for (int i = 0; i < 4; i++) {
            const int row = by * 128 + ih * 64 + ty * 4 + i;
            #pragma unroll
            for (int jh = 0; jh < 2; jh++) {
                const int col = bx * 128 + jh * 64 + tx * 4;
                float4 v;
                v.x = acc[ih * 4 + i][jh * 4 + 0];
                v.y = acc[ih * 4 + i][jh * 4 + 1];
                v.z = acc[ih * 4 + i][jh * 4 + 2];
                v.w = acc[ih * 4 + i][jh * 4 + 3];
                if (BIAS) {
                    v.x += bias[col + 0];
                    v.y += bias[col + 1];
                    v.z += bias[col + 2];
                    v.w += bias[col + 3];
                }
                *(float4*)&C[(size_t)row * N + col] = v;
            }
        }
}

// ---------------- RoPE on k half of g_kv (in place) -------------------------
__global__ __launch_bounds__(256) void rope_kernel(
    const float* __restrict__ cosb, const float* __restrict__ sinb)
{
    const int idx = blockIdx.x * 256 + threadIdx.x;   // over BATCH*SEQ*HEADS*32
    const int d2 = idx & 31;
    const int h  = (idx >> 5) & 15;
    const int s  = (idx >> 9) & 4095;
    const int b  = idx >> 21;
    const size_t base = ((size_t)(b * SEQ + s)) * (2 * INNER) + h * DHEAD;
    const float k1 = g_kv[base + d2];
    const float k2 = g_kv[base + 32 + d2];
    const float c  = cosb[s * 32 + d2];
    const float sn = sinb[s * 32 + d2];
    g_kv[base + d2]      = k1 * c - k2 * sn;
    g_kv[base + 32 + d2] = k2 * c + k1 * sn;
}

// ---------------- Flash attention: 64 q-rows x 64 s-cols tiles --------------
#define LDP 68   // float pitch; 17 (16B units) is odd mod 8 -> conflict-free LDS.128

extern __shared__ float at_smem[];
__global__ __launch_bounds__(256) void attn_kernel()
{
    float* Qs = at_smem;            // 64*LDP
    float* Ks = Qs + 64 * LDP;
    float* Vs = Ks + 64 * LDP;
    float* Ps = Vs + 64 * LDP;

    const int bh = blockIdx.y;
    const int b = bh >> 4, h = bh & 15;
    const int n0 = blockIdx.x * 64;
    const int t = threadIdx.x;
    const int tx = t & 15, ty = t >> 4;
    const float scale = 0.125f;     // 1/sqrt(64)

    // load Q tile (64 x 64)
    #pragma unroll
    for (int i = 0; i < 4; i++) {
        const int lin = t + 256 * i;                   // float4 slot 0..1023
        const int r = lin >> 4, c4 = (lin & 15) * 4;
        *(float4*)&Qs[r * LDP + c4] =
            *(const float4*)&g_q[((size_t)(b * NLAT + n0 + r)) * INNER + h * DHEAD + c4];
    }

    float m_i[4], l_i[4], o[4][4];
    #pragma unroll
    for (int i = 0; i < 4; i++) {
        m_i[i] = -1e30f; l_i[i] = 0.f;
        #pragma unroll
        for (int j = 0; j < 4; j++) o[i][j] = 0.f;
    }

    for (int s0 = 0; s0 < SEQ; s0 += 64) {
        __syncthreads();   // protect Ks/Vs/Ps reuse (and Q load on first iter)
        #pragma unroll
        for (int i = 0; i < 4; i++) {
            const int lin = t + 256 * i;
            const int r = lin >> 4, c4 = (lin & 15) * 4;
            const size_t gb = ((size_t)(b * SEQ + s0 + r)) * (2 * INNER) + h * DHEAD + c4;
            *(float4*)&Ks[r * LDP + c4] = *(const float4*)&g_kv[gb];
            *(float4*)&Vs[r * LDP + c4] = *(const float4*)&g_kv[gb + INNER];
        }
        __syncthreads();

        // S = Q K^T  (rows ty*4+i, cols tx+16j)
        float sacc[4][4];
        #pragma unroll
        for (int i = 0; i < 4; i++)
            #pragma unroll
            for (int j = 0; j < 4; j++) sacc[i][j] = 0.f;

        #pragma unroll
        for (int d = 0; d < 64; d += 4) {
            float4 aq[4], bk[4];
            #pragma unroll
            for (int i = 0; i < 4; i++) aq[i] = *(float4*)&Qs[(ty * 4 + i) * LDP + d];
            #pragma unroll
            for (int j = 0; j < 4; j++) bk[j] = *(float4*)&Ks[(tx + 16 * j) * LDP + d];
            #pragma unroll
            for (int i = 0; i < 4; i++)
                #pragma unroll
                for (int j = 0; j < 4; j++)
                    sacc[i][j] += aq[i].x * bk[j].x + aq[i].y * bk[j].y +
                                  aq[i].z * bk[j].z + aq[i].w * bk[j].w;
        }

        // scale + clip + online softmax state update
        #pragma unroll
        for (int i = 0; i < 4; i++) {
            float mloc = -1e30f;
            #pragma unroll
            for (int j = 0; j < 4; j++) {
                float v = sacc[i][j] * scale;
                v = fminf(11.0f, fmaxf(-11.0f, v));
                sacc[i][j] = v;
                mloc = fmaxf(mloc, v);
            }
            #pragma unroll
            for (int off = 8; off; off >>= 1)
                mloc = fmaxf(mloc, __shfl_xor_sync(0xffffffffu, mloc, off, 16));
            const float mnew = fmaxf(m_i[i], mloc);
            const float corr = __expf(m_i[i] - mnew);
            float psum = 0.f;
            #pragma unroll
            for (int j = 0; j < 4; j++) {
                const float p = __expf(sacc[i][j] - mnew);
                sacc[i][j] = p;
                psum += p;
            }
            #pragma unroll
            for (int off = 8; off; off >>= 1)
                psum += __shfl_xor_sync(0xffffffffu, psum, off, 16);
            l_i[i] = l_i[i] * corr + psum;
            m_i[i] = mnew;
            #pragma unroll
            for (int j = 0; j < 4; j++) {
                o[i][j] *= corr;
                Ps[(ty * 4 + i) * LDP + tx + 16 * j] = sacc[i][j];
            }
        }
        __syncthreads();

        // O += P V
        #pragma unroll 4
        for (int ss = 0; ss < 64; ss++) {
            float pvv[4], vv[4];
            #pragma unroll
            for (int i = 0; i < 4; i++) pvv[i] = Ps[(ty * 4 + i) * LDP + ss];
            #pragma unroll
            for (int j = 0; j < 4; j++) vv[j] = Vs[ss * LDP + tx + 16 * j];
            #pragma unroll
            for (int i = 0; i < 4; i++)
                #pragma unroll
                for (int j = 0; j < 4; j++) o[i][j] += pvv[i] * vv[j];
        }
    }

    // finalize + write [b*256+n, h*64+d] layout
    #pragma unroll
    for (int i = 0; i < 4; i++) {
        const float inv = 1.0f / l_i[i];
        const size_t row = (size_t)(b * NLAT + n0 + ty * 4 + i) * INNER + h * DHEAD;
        #pragma unroll
        for (int j = 0; j < 4; j++)
            g_attn[row + tx + 16 * j] = o[i][j] * inv;
    }
}

// ---------------- host launcher --------------------------------------------
extern "C" void kernel_launch(void* const* d_in, const int* in_sizes, int n_in,
                              void* d_out, int out_size)
{
    const float* latents  = (const float*)d_in[0];
    const float* context  = (const float*)d_in[1];
    const float* cosb     = (const float*)d_in[2];
    const float* sinb     = (const float*)d_in[3];
    const float* ln_lat_g = (const float*)d_in[4];
    const float* ln_lat_b = (const float*)d_in[5];
    const float* ln_ctx_g = (const float*)d_in[6];
    const float* ln_ctx_b = (const float*)d_in[7];
    const float* Wq       = (const float*)d_in[8];
    const float* Wkv      = (const float*)d_in[9];
    const float* Wo       = (const float*)d_in[10];
    const float* bo       = (const float*)d_in[11];
    float* out = (float*)d_out;

    float *lat_n, *ctx_n, *q, *kv, *attn;
    cudaGetSymbolAddress((void**)&lat_n, g_lat_n);
    cudaGetSymbolAddress((void**)&ctx_n, g_ctx_n);
    cudaGetSymbolAddress((void**)&q,     g_q);
    cudaGetSymbolAddress((void**)&kv,    g_kv);
    cudaGetSymbolAddress((void**)&attn,  g_attn);

    // 1. LayerNorms
    ln_kernel<<<BATCH * NLAT, 256>>>(latents, ln_lat_g, ln_lat_b, lat_n);
    ln_kernel<<<BATCH * SEQ,  256>>>(context, ln_ctx_g, ln_ctx_b, ctx_n);

    // 2. Projections
    sgemm128<false><<<dim3(INNER / 128, (BATCH * NLAT) / 128), 256>>>(
        lat_n, Wq, nullptr, q, BATCH * NLAT, INNER, DIM);
    sgemm128<false><<<dim3((2 * INNER) / 128, (BATCH * SEQ) / 128), 256>>>(
        ctx_n, Wkv, nullptr, kv, BATCH * SEQ, 2 * INNER, DIM);

    // 3. RoPE on k
    rope_kernel<<<(BATCH * SEQ * HEADS * 32) / 256, 256>>>(cosb, sinb);

    // 4. Attention
    const int at_smem_bytes = 4 * 64 * LDP * (int)sizeof(float);  // 69632
    cudaFuncSetAttribute(attn_kernel, cudaFuncAttributeMaxDynamicSharedMemorySize,
                         at_smem_bytes);
    attn_kernel<<<dim3(NLAT / 64, BATCH * HEADS), 256, at_smem_bytes>>>();

    // 5. Output projection + bias
    sgemm128<true><<<dim3(DIM / 128, (BATCH * NLAT) / 128), 256>>>(
        attn, Wo, bo, out, BATCH * NLAT, DIM, INNER);
}

// round 5
// speedup vs baseline: 2.6584x; 2.6584x over previous
#include <cuda_runtime.h>
#include <cuda_bf16.h>
#include <math.h>
#include <stdint.h>

#define BATCH 8
#define NLAT  256
#define SEQ   4096
#define DIM   1024
#define HEADS 16
#define DHEAD 64
#define INNER 1024
#define EPSLN 1e-5f

// ---- kv GEMM geometry: C[32768,2048] = A[32768,1024] x W[1024,2048]
#define GM     (BATCH * SEQ)      // 32768
#define GN     (2 * INNER)        // 2048
#define MT     (GM / 128)         // 256 m tiles
#define NT     (GN / 128)         // 16 n tiles
#define KCH    (DIM / 64)         // 16 k chunks of 64
#define BLK    16384              // one 128row x 128B swizzled block
#define NSTG   3
#define STG_BYTES (4 * BLK)       // Ah|Al|Bh|Bl = 64KB per stage

// ---------------- scratch (device globals: no runtime allocation) ----------
__device__ float g_lat_n[BATCH * NLAT * DIM];                 //   8 MB
__device__ float g_q[BATCH * NLAT * INNER];                   //   8 MB
__device__ float g_kv[(size_t)BATCH * SEQ * 2 * INNER];       // 256 MB (k | v)
__device__ float g_attn[BATCH * NLAT * INNER];                //   8 MB
__device__ uint4 g_A[(size_t)MT * KCH * 2 * BLK / 16];        // 134 MB split-bf16 A
__device__ uint4 g_B[(size_t)NT * KCH * 2 * BLK / 16];        //   8 MB split-bf16 Wt

// ---------------- PTX helpers ----------------------------------------------
__device__ __forceinline__ uint32_t smem_u32(const void* p) {
    uint32_t a;
    asm("{ .reg .u64 t; cvta.to.shared.u64 t, %1; cvt.u32.u64 %0, t; }"
        : "=r"(a) : "l"(p));
    return a;
}
__device__ __forceinline__ void mbar_init(uint32_t m, uint32_t cnt) {
    asm volatile("mbarrier.init.shared.b64 [%0], %1;" :: "r"(m), "r"(cnt) : "memory");
}
__device__ __forceinline__ void mbar_expect(uint32_t m, uint32_t bytes) {
    asm volatile("mbarrier.arrive.expect_tx.shared.b64 _, [%0], %1;"
                 :: "r"(m), "r"(bytes) : "memory");
}
__device__ __forceinline__ void mbar_wait(uint32_t m, int ph) {
    asm volatile(
        "{\n\t.reg .pred P;\n\t"
        "W%=:\n\t"
        "mbarrier.try_wait.parity.shared.b64 P, [%0], %1;\n\t"
        "@!P bra W%=;\n\t}"
        :: "r"(m), "r"(ph) : "memory");
}
__device__ __forceinline__ void bulk_g2s(uint32_t dst, const void* src,
                                         uint32_t bytes, uint32_t mbar) {
    asm volatile(
        "cp.async.bulk.shared::cluster.global.mbarrier::complete_tx::bytes "
        "[%0], [%1], %2, [%3];"
        :: "r"(dst), "l"(src), "r"(bytes), "r"(mbar) : "memory");
}
__device__ __forceinline__ void ldmx4(uint32_t* r, uint32_t addr) {
    asm volatile("ldmatrix.sync.aligned.m8n8.x4.shared.b16 {%0,%1,%2,%3}, [%4];"
                 : "=r"(r[0]), "=r"(r[1]), "=r"(r[2]), "=r"(r[3]) : "r"(addr));
}
__device__ __forceinline__ void mma16816(float* c, const uint32_t* a,
                                         uint32_t b0, uint32_t b1) {
    asm volatile(
        "mma.sync.aligned.m16n8k16.row.col.f32.bf16.bf16.f32 "
        "{%0,%1,%2,%3}, {%4,%5,%6,%7}, {%8,%9}, {%0,%1,%2,%3};"
        : "+f"(c[0]), "+f"(c[1]), "+f"(c[2]), "+f"(c[3])
        : "r"(a[0]), "r"(a[1]), "r"(a[2]), "r"(a[3]), "r"(b0), "r"(b1));
}

// ---------------- LayerNorm (fp32 out) for latents --------------------------
__global__ __launch_bounds__(256) void ln_kernel(
    const float* __restrict__ x, const float* __restrict__ gam,
    const float* __restrict__ bet, float* __restrict__ y)
{
    const int row = blockIdx.x;
    const int t = threadIdx.x;
    __shared__ float red[8];

    const float4 v = ((const float4*)(x + (size_t)row * DIM))[t];
    float s = v.x + v.y + v.z + v.w;
    #pragma unroll
    for (int off = 16; off; off >>= 1) s += __shfl_xor_sync(0xffffffffu, s, off);
    if ((t & 31) == 0) red[t >> 5] = s;
    __syncthreads();
    if (t < 8) {
        float r = red[t];
        #pragma unroll
        for (int off = 4; off; off >>= 1) r += __shfl_xor_sync(0xffu, r, off);
        if (t == 0) red[0] = r;
    }
    __syncthreads();
    const float mu = red[0] * (1.0f / DIM);
    const float dx = v.x - mu, dy = v.y - mu, dz = v.z - mu, dw = v.w - mu;
    float s2 = dx * dx + dy * dy + dz * dz + dw * dw;
    __syncthreads();
    #pragma unroll
    for (int off = 16; off; off >>= 1) s2 += __shfl_xor_sync(0xffffffffu, s2, off);
    if ((t & 31) == 0) red[t >> 5] = s2;
    __syncthreads();
    if (t < 8) {
        float r = red[t];
        #pragma unroll
        for (int off = 4; off; off >>= 1) r += __shfl_xor_sync(0xffu, r, off);
        if (t == 0) red[0] = r;
    }
    __syncthreads();
    const float rs = rsqrtf(red[0] * (1.0f / DIM) + EPSLN);

    const float4 gg = ((const float4*)gam)[t];
    const float4 bb = ((const float4*)bet)[t];
    float4 o;
    o.x = dx * rs * gg.x + bb.x;
    o.y = dy * rs * gg.y + bb.y;
    o.z = dz * rs * gg.z + bb.z;
    o.w = dw * rs * gg.w + bb.w;
    ((float4*)(y + (size_t)row * DIM))[t] = o;
}

// -------- LayerNorm for context, fused with split-bf16 tiled/swizzled prep --
__global__ __launch_bounds__(256) void ln_ctx_prep_kernel(
    const float* __restrict__ x, const float* __restrict__ gam,
    const float* __restrict__ bet)
{
    const int row = blockIdx.x;          // m index 0..32767
    const int t = threadIdx.x;
    __shared__ float red[8];

    const float4 v = ((const float4*)(x + (size_t)row * DIM))[t];
    float s = v.x + v.y + v.z + v.w;
    #pragma unroll
    for (int off = 16; off; off >>= 1) s += __shfl_xor_sync(0xffffffffu, s, off);
    if ((t & 31) == 0) red[t >> 5] = s;
    __syncthreads();
    if (t < 8) {
        float r = red[t];
        #pragma unroll
        for (int off = 4; off; off >>= 1) r += __shfl_xor_sync(0xffu, r, off);
        if (t == 0) red[0] = r;
    }
    __syncthreads();
    const float mu = red[0] * (1.0f / DIM);
    const float dx = v.x - mu, dy = v.y - mu, dz = v.z - mu, dw = v.w - mu;
    float s2 = dx * dx + dy * dy + dz * dz + dw * dw;
    __syncthreads();
    #pragma unroll
    for (int off = 16; off; off >>= 1) s2 += __shfl_xor_sync(0xffffffffu, s2, off);
    if ((t & 31) == 0) red[t >> 5] = s2;
    __syncthreads();
    if (t < 8) {
        float r = red[t];
        #pragma unroll
        for (int off = 4; off; off >>= 1) r += __shfl_xor_sync(0xffu, r, off);
        if (t == 0) red[0] = r;
    }
    __syncthreads();
    const float rs = rsqrtf(red[0] * (1.0f / DIM) + EPSLN);

    const float4 gg = ((const float4*)gam)[t];
    const float4 bb = ((const float4*)bet)[t];
    float o0 = dx * rs * gg.x + bb.x;
    float o1 = dy * rs * gg.y + bb.y;
    float o2 = dz * rs * gg.z + bb.z;
    float o3 = dw * rs * gg.w + bb.w;

    // split into hi/lo bf16 and write to tiled+swizzled g_A
    __nv_bfloat16 h0 = __float2bfloat16(o0), h1 = __float2bfloat16(o1);
    __nv_bfloat16 h2 = __float2bfloat16(o2), h3 = __float2bfloat16(o3);
    __nv_bfloat16 l0 = __float2bfloat16(o0 - __bfloat162float(h0));
    __nv_bfloat16 l1 = __float2bfloat16(o1 - __bfloat162float(h1));
    __nv_bfloat16 l2 = __float2bfloat16(o2 - __bfloat162float(h2));
    __nv_bfloat16 l3 = __float2bfloat16(o3 - __bfloat162float(h3));

    const int mt = row >> 7, r = row & 127;
    const int chunk = t >> 4;            // k chunk (64 elems)
    const int c = (t & 15) * 4;          // col within chunk
    uint32_t bo = (uint32_t)(r * 128 + c * 2);
    uint32_t sw = bo ^ ((bo >> 3) & 0x70);
    char* dst = (char*)g_A + ((size_t)(mt * KCH + chunk) * 2) * BLK + sw;

    uint2 hv, lv;
    hv.x = (uint32_t)__bfloat16_as_ushort(h0) | ((uint32_t)__bfloat16_as_ushort(h1) << 16);
    hv.y = (uint32_t)__bfloat16_as_ushort(h2) | ((uint32_t)__bfloat16_as_ushort(h3) << 16);
    lv.x = (uint32_t)__bfloat16_as_ushort(l0) | ((uint32_t)__bfloat16_as_ushort(l1) << 16);
    lv.y = (uint32_t)__bfloat16_as_ushort(l2) | ((uint32_t)__bfloat16_as_ushort(l3) << 16);
    *(uint2*)dst = hv;
    *(uint2*)(dst + BLK) = lv;
}

// -------- Wkv -> split-bf16, transposed to K-major, tiled/swizzled ----------
__global__ __launch_bounds__(256) void bprep_kernel(const float* __restrict__ Wkv)
{
    const int idx = blockIdx.x * 256 + threadIdx.x;   // k*2048 + n
    const int n = idx & (GN - 1);
    const int k = idx >> 11;
    const float wv = Wkv[idx];
    __nv_bfloat16 h = __float2bfloat16(wv);
    __nv_bfloat16 l = __float2bfloat16(wv - __bfloat162float(h));
    const int nt = n >> 7, r = n & 127, chunk = k >> 6, c = k & 63;
    uint32_t bo = (uint32_t)(r * 128 + c * 2);
    uint32_t sw = bo ^ ((bo >> 3) & 0x70);
    char* dst = (char*)g_B + ((size_t)(nt * KCH + chunk) * 2) * BLK + sw;
    *(unsigned short*)dst = __bfloat16_as_ushort(h);
    *(unsigned short*)(dst + BLK) = __bfloat16_as_ushort(l);
}

// -------- kv GEMM: mma.sync bf16 split, 128x128 tile, 3-stage pipeline ------
// dyn smem: [0..24) full mbar x3, stages @ 1024
#define OFF_FULL 0
#define OFF_STG  1024

extern __shared__ char kv_smem[];
__global__ __launch_bounds__(256) void kv_mma_kernel()
{
    const uint32_t sb = smem_u32(kv_smem);
    const int t = threadIdx.x;
    const int w = t >> 5, lane = t & 31;
    const int bx = blockIdx.x, by = blockIdx.y;
    const int wm = w & 3, wn = w >> 2;          // 4 x 2 warp grid
    const int g = lane >> 2, tig = lane & 3;

    if (t == 0) {
        #pragma unroll
        for (int i = 0; i < NSTG; i++) mbar_init(sb + OFF_FULL + 8 * i, 1);
    }
    __syncthreads();
    asm volatile("fence.proxy.async.shared::cta;" ::: "memory");

    const char* Ab = (const char*)g_A + (size_t)by * KCH * 2 * BLK;
    const char* Bb = (const char*)g_B + (size_t)bx * KCH * 2 * BLK;

    if (t == 0) {
        #pragma unroll
        for (int c = 0; c < NSTG; c++) {
            uint32_t st = sb + OFF_STG + c * STG_BYTES;
            mbar_expect(sb + OFF_FULL + 8 * c, STG_BYTES);
            bulk_g2s(st,           Ab + (size_t)c * 2 * BLK, 2 * BLK, sb + OFF_FULL + 8 * c);
            bulk_g2s(st + 2 * BLK, Bb + (size_t)c * 2 * BLK, 2 * BLK, sb + OFF_FULL + 8 * c);
        }
    }

    // per-lane ldmatrix addressing (SW128: xor mask = (row&7)<<4, row<128)
    const int l15 = lane & 15;
    const uint32_t kb16 = (uint32_t)(lane & 16);          // +16B for k8..15 half
    const uint32_t mask = (uint32_t)((lane & 7) << 4);
    uint32_t aoff[2], boff[4];
    #pragma unroll
    for (int mi = 0; mi < 2; mi++) aoff[mi] = (uint32_t)((wm * 32 + mi * 16 + l15) * 128);
    #pragma unroll
    for (int p = 0; p < 4; p++)    boff[p]  = (uint32_t)((wn * 64 + p * 16 + l15) * 128);

    float acc[2][8][4];
    #pragma unroll
    for (int mi = 0; mi < 2; mi++)
        #pragma unroll
        for (int ni = 0; ni < 8; ni++)
            #pragma unroll
            for (int q = 0; q < 4; q++) acc[mi][ni][q] = 0.f;

    int ph[NSTG] = {0, 0, 0};

    for (int kc = 0; kc < KCH; kc++) {
        const int s = kc % NSTG;
        mbar_wait(sb + OFF_FULL + 8 * s, ph[s]); ph[s] ^= 1;
        const uint32_t base = sb + OFF_STG + s * STG_BYTES;

        #pragma unroll
        for (int ks = 0; ks < 4; ks++) {
            const uint32_t kx = ((uint32_t)(ks * 32) + kb16) ^ mask;
            uint32_t ah[2][4], al[2][4], bh[4][4], bl[4][4];
            #pragma unroll
            for (int mi = 0; mi < 2; mi++) {
                ldmx4(ah[mi], base + aoff[mi] + kx);
                ldmx4(al[mi], base + BLK + aoff[mi] + kx);
            }
            #pragma unroll
            for (int p = 0; p < 4; p++) {
                ldmx4(bh[p], base + 2 * BLK + boff[p] + kx);
                ldmx4(bl[p], base + 3 * BLK + boff[p] + kx);
            }
            // bX[p] regs: {b0 of tile 2p, b0 of tile 2p+1, b1 of tile 2p, b1 of tile 2p+1}
            #pragma unroll
            for (int mi = 0; mi < 2; mi++)
                #pragma unroll
                for (int p = 0; p < 4; p++) {
                    mma16816(acc[mi][2 * p + 0], ah[mi], bh[p][0], bh[p][2]);
                    mma16816(acc[mi][2 * p + 1], ah[mi], bh[p][1], bh[p][3]);
                    mma16816(acc[mi][2 * p + 0], ah[mi], bl[p][0], bl[p][2]);
                    mma16816(acc[mi][2 * p + 1], ah[mi], bl[p][1], bl[p][3]);
                    mma16816(acc[mi][2 * p + 0], al[mi], bh[p][0], bh[p][2]);
                    mma16816(acc[mi][2 * p + 1], al[mi], bh[p][1], bh[p][3]);
                }
        }
        __syncthreads();   // all warps done with stage s before reload
        const int nxt = kc + NSTG;
        if (t == 0 && nxt < KCH) {
            mbar_expect(sb + OFF_FULL + 8 * s, STG_BYTES);
            bulk_g2s(base,           Ab + (size_t)nxt * 2 * BLK, 2 * BLK, sb + OFF_FULL + 8 * s);
            bulk_g2s(base + 2 * BLK, Bb + (size_t)nxt * 2 * BLK, 2 * BLK, sb + OFF_FULL + 8 * s);
        }
    }

    // epilogue: mma fragment -> g_kv (fp32)
    #pragma unroll
    for (int mi = 0; mi < 2; mi++) {
        const int row0 = by * 128 + wm * 32 + mi * 16 + g;
        #pragma unroll
        for (int ni = 0; ni < 8; ni++) {
            const int col = bx * 128 + wn * 64 + ni * 8 + tig * 2;
            float2 v0 = make_float2(acc[mi][ni][0], acc[mi][ni][1]);
            float2 v1 = make_float2(acc[mi][ni][2], acc[mi][ni][3]);
            *(float2*)&g_kv[(size_t)row0 * GN + col] = v0;
            *(float2*)&g_kv[(size_t)(row0 + 8) * GN + col] = v1;
        }
    }
}

// ---------------- SGEMM 128x128x8 (q and output projections) ---------------
template <bool BIAS>
__global__ __launch_bounds__(256) void sgemm128(
    const float* __restrict__ A, const float* __restrict__ Bm,
    const float* __restrict__ bias, float* __restrict__ C,
    int M, int N, int K)
{
    __shared__ float As[8][128];
    __shared__ float Bs[8][128];

    const int tid = threadIdx.x;
    const int tx = tid & 15, ty = tid >> 4;
    const int bx = blockIdx.x, by = blockIdx.y;

    const int arow = tid >> 1,  acol = (tid & 1) * 4;
    const int brow = tid >> 5,  bcol = (tid & 31) * 4;
    const float* Aptr = A + (size_t)(by * 128 + arow) * K + acol;
    const float* Bptr = Bm + (size_t)brow * N + bx * 128 + bcol;

    float acc[8][8];
    #pragma unroll
    for (int i = 0; i < 8; i++)
        #pragma unroll
        for (int j = 0; j < 8; j++) acc[i][j] = 0.f;

    for (int k0 = 0; k0 < K; k0 += 8) {
        const float4 av = *(const float4*)(Aptr + k0);
        const float4 bv = *(const float4*)(Bptr + (size_t)k0 * N);
        As[acol + 0][arow] = av.x;
        As[acol + 1][arow] = av.y;
        As[acol + 2][arow] = av.z;
        As[acol + 3][arow] = av.w;
        *(float4*)&Bs[brow][bcol] = bv;
        __syncthreads();

        #pragma unroll
        for (int kk = 0; kk < 8; kk++) {
            const float4 a0 = *(float4*)&As[kk][ty * 4];
            const float4 a1 = *(float4*)&As[kk][64 + ty * 4];
            const float4 b0 = *(float4*)&Bs[kk][tx * 4];
            const float4 b1 = *(float4*)&Bs[kk][64 + tx * 4];
            const float a[8] = {a0.x, a0.y, a0.z, a0.w, a1.x, a1.y, a1.z, a1.w};
            const float b[8] = {b0.x, b0.y, b0.z, b0.w, b1.x, b1.y, b1.z, b1.w};
            #pragma unroll
            for (int i = 0; i < 8; i++)
                #pragma unroll
                for (int j = 0; j < 8; j++) acc[i][j] += a[i] * b[j];
        }
        __syncthreads();
    }

    #pragma unroll
    for (int ih = 0; ih < 2; ih++)
        #pragma unroll
        for (int i = 0; i < 4; i++) {
            const int row = by * 128 + ih * 64 + ty * 4 + i;
            #pragma unroll
            for (int jh = 0; jh < 2; jh++) {
                const int col = bx * 128 + jh * 64 + tx * 4;
                float4 v;
                v.x = acc[ih * 4 + i][jh * 4 + 0];
                v.y = acc[ih * 4 + i][jh * 4 + 1];
                v.z = acc[ih * 4 + i][jh * 4 + 2];
                v.w = acc[ih * 4 + i][jh * 4 + 3];
                if (BIAS) {
                    v.x += bias[col + 0];
                    v.y += bias[col + 1];
                    v.z += bias[col + 2];
                    v.w += bias[col + 3];
                }
                *(float4*)&C[(size_t)row * N + col] = v;
            }
        }
}

// ---------------- RoPE on k half of g_kv (in place) -------------------------
__global__ __launch_bounds__(256) void rope_kernel(
    const float* __restrict__ cosb, const float* __restrict__ sinb)
{
    const int idx = blockIdx.x * 256 + threadIdx.x;
    const int d2 = idx & 31;
    const int h  = (idx >> 5) & 15;
    const int s  = (idx >> 9) & 4095;
    const int b  = idx >> 21;
    const size_t base = ((size_t)(b * SEQ + s)) * (2 * INNER) + h * DHEAD;
    const float k1 = g_kv[base + d2];
    const float k2 = g_kv[base + 32 + d2];
    const float c  = cosb[s * 32 + d2];
    const float sn = sinb[s * 32 + d2];
    g_kv[base + d2]      = k1 * c - k2 * sn;
    g_kv[base + 32 + d2] = k2 * c + k1 * sn;
}

// ---------------- Flash attention: 64 q-rows x 64 s-cols tiles --------------
#define LDP 68

extern __shared__ float at_smem[];
__global__ __launch_bounds__(256) void attn_kernel()
{
    float* Qs = at_smem;
    float* Ks = Qs + 64 * LDP;
    float* Vs = Ks + 64 * LDP;
    float* Ps = Vs + 64 * LDP;

    const int bh = blockIdx.y;
    const int b = bh >> 4, h = bh & 15;
    const int n0 = blockIdx.x * 64;
    const int t = threadIdx.x;
    const int tx = t & 15, ty = t >> 4;
    const float scale = 0.125f;

    #pragma unroll
    for (int i = 0; i < 4; i++) {
        const int lin = t + 256 * i;
        const int r = lin >> 4, c4 = (lin & 15) * 4;
        *(float4*)&Qs[r * LDP + c4] =
            *(const float4*)&g_q[((size_t)(b * NLAT + n0 + r)) * INNER + h * DHEAD + c4];
    }

    float m_i[4], l_i[4], o[4][4];
    #pragma unroll
    for (int i = 0; i < 4; i++) {
        m_i[i] = -1e30f; l_i[i] = 0.f;
        #pragma unroll
        for (int j = 0; j < 4; j++) o[i][j] = 0.f;
    }

    for (int s0 = 0; s0 < SEQ; s0 += 64) {
        __syncthreads();
        #pragma unroll
        for (int i = 0; i < 4; i++) {
            const int lin = t + 256 * i;
            const int r = lin >> 4, c4 = (lin & 15) * 4;
            const size_t gb = ((size_t)(b * SEQ + s0 + r)) * (2 * INNER) + h * DHEAD + c4;
            *(float4*)&Ks[r * LDP + c4] = *(const float4*)&g_kv[gb];
            *(float4*)&Vs[r * LDP + c4] = *(const float4*)&g_kv[gb + INNER];
        }
        __syncthreads();

        float sacc[4][4];
        #pragma unroll
        for (int i = 0; i < 4; i++)
            #pragma unroll
            for (int j = 0; j < 4; j++) sacc[i][j] = 0.f;

        #pragma unroll
        for (int d = 0; d < 64; d += 4) {
            float4 aq[4], bk[4];
            #pragma unroll
            for (int i = 0; i < 4; i++) aq[i] = *(float4*)&Qs[(ty * 4 + i) * LDP + d];
            #pragma unroll
            for (int j = 0; j < 4; j++) bk[j] = *(float4*)&Ks[(tx + 16 * j) * LDP + d];
            #pragma unroll
            for (int i = 0; i < 4; i++)
                #pragma unroll
                for (int j = 0; j < 4; j++)
                    sacc[i][j] += aq[i].x * bk[j].x + aq[i].y * bk[j].y +
                                  aq[i].z * bk[j].z + aq[i].w * bk[j].w;
        }

        #pragma unroll
        for (int i = 0; i < 4; i++) {
            float mloc = -1e30f;
            #pragma unroll
            for (int j = 0; j < 4; j++) {
                float v = sacc[i][j] * scale;
                v = fminf(11.0f, fmaxf(-11.0f, v));
                sacc[i][j] = v;
                mloc = fmaxf(mloc, v);
            }
            #pragma unroll
            for (int off = 8; off; off >>= 1)
                mloc = fmaxf(mloc, __shfl_xor_sync(0xffffffffu, mloc, off, 16));
            const float mnew = fmaxf(m_i[i], mloc);
            const float corr = __expf(m_i[i] - mnew);
            float psum = 0.f;
            #pragma unroll
            for (int j = 0; j < 4; j++) {
                const float p = __expf(sacc[i][j] - mnew);
                sacc[i][j] = p;
                psum += p;
            }
            #pragma unroll
            for (int off = 8; off; off >>= 1)
                psum += __shfl_xor_sync(0xffffffffu, psum, off, 16);
            l_i[i] = l_i[i] * corr + psum;
            m_i[i] = mnew;
            #pragma unroll
            for (int j = 0; j < 4; j++) {
                o[i][j] *= corr;
                Ps[(ty * 4 + i) * LDP + tx + 16 * j] = sacc[i][j];
            }
        }
        __syncthreads();

        #pragma unroll 4
        for (int ss = 0; ss < 64; ss++) {
            float pvv[4], vv[4];
            #pragma unroll
            for (int i = 0; i < 4; i++) pvv[i] = Ps[(ty * 4 + i) * LDP + ss];
            #pragma unroll
            for (int j = 0; j < 4; j++) vv[j] = Vs[ss * LDP + tx + 16 * j];
            #pragma unroll
            for (int i = 0; i < 4; i++)
                #pragma unroll
                for (int j = 0; j < 4; j++) o[i][j] += pvv[i] * vv[j];
        }
    }

    #pragma unroll
    for (int i = 0; i < 4; i++) {
        const float inv = 1.0f / l_i[i];
        const size_t row = (size_t)(b * NLAT + n0 + ty * 4 + i) * INNER + h * DHEAD;
        #pragma unroll
        for (int j = 0; j < 4; j++)
            g_attn[row + tx + 16 * j] = o[i][j] * inv;
    }
}

// ---------------- host launcher --------------------------------------------
extern "C" void kernel_launch(void* const* d_in, const int* in_sizes, int n_in,
                              void* d_out, int out_size)
{
    const float* latents  = (const float*)d_in[0];
    const float* context  = (const float*)d_in[1];
    const float* cosb     = (const float*)d_in[2];
    const float* sinb     = (const float*)d_in[3];
    const float* ln_lat_g = (const float*)d_in[4];
    const float* ln_lat_b = (const float*)d_in[5];
    const float* ln_ctx_g = (const float*)d_in[6];
    const float* ln_ctx_b = (const float*)d_in[7];
    const float* Wq       = (const float*)d_in[8];
    const float* Wkv      = (const float*)d_in[9];
    const float* Wo       = (const float*)d_in[10];
    const float* bo       = (const float*)d_in[11];
    float* out = (float*)d_out;

    float *lat_n, *q, *kv, *attn;
    cudaGetSymbolAddress((void**)&lat_n, g_lat_n);
    cudaGetSymbolAddress((void**)&q,     g_q);
    cudaGetSymbolAddress((void**)&kv,    g_kv);
    cudaGetSymbolAddress((void**)&attn,  g_attn);

    // 1. LayerNorms (ctx LN fused with split-bf16 tiled prep)
    ln_kernel<<<BATCH * NLAT, 256>>>(latents, ln_lat_g, ln_lat_b, lat_n);
    ln_ctx_prep_kernel<<<BATCH * SEQ, 256>>>(context, ln_ctx_g, ln_ctx_b);
    bprep_kernel<<<(DIM * GN) / 256, 256>>>(Wkv);

    // 2. q projection (fp32 sgemm)
    sgemm128<false><<<dim3(INNER / 128, (BATCH * NLAT) / 128), 256>>>(
        lat_n, Wq, nullptr, q, BATCH * NLAT, INNER, DIM);

    // 3. kv projection on tensor cores (mma.sync bf16 split)
    const int kv_smem_bytes = OFF_STG + NSTG * STG_BYTES;   // 197632
    cudaFuncSetAttribute(kv_mma_kernel, cudaFuncAttributeMaxDynamicSharedMemorySize,
                         kv_smem_bytes);
    kv_mma_kernel<<<dim3(NT, MT), 256, kv_smem_bytes>>>();

    // 4. RoPE on k
    rope_kernel<<<(BATCH * SEQ * HEADS * 32) / 256, 256>>>(cosb, sinb);

    // 5. Attention
    const int at_smem_bytes = 4 * 64 * LDP * (int)sizeof(float);
    cudaFuncSetAttribute(attn_kernel, cudaFuncAttributeMaxDynamicSharedMemorySize,
                         at_smem_bytes);
    attn_kernel<<<dim3(NLAT / 64, BATCH * HEADS), 256, at_smem_bytes>>>();

    // 6. Output projection + bias
    sgemm128<true><<<dim3(DIM / 128, (BATCH * NLAT) / 128), 256>>>(
        attn, Wo, bo, out, BATCH * NLAT, DIM, INNER);
}

// round 9
// speedup vs baseline: 3.7269x; 1.4019x over previous
#include <cuda_runtime.h>
#include <cuda_bf16.h>
#include <math.h>
#include <stdint.h>

#define BATCH 8
#define NLAT  256
#define SEQ   4096
#define DIM   1024
#define HEADS 16
#define DHEAD 64
#define INNER 1024
#define EPSLN 1e-5f
#define BH    (BATCH * HEADS)     // 128

// ---- kv GEMM geometry: C[32768,2048] = A[32768,1024] x W[1024,2048]
#define GM     (BATCH * SEQ)      // 32768
#define GN     (2 * INNER)        // 2048
#define MT     (GM / 128)         // 256 m tiles
#define NT     (GN / 128)         // 16 n tiles
#define KCH    (DIM / 64)         // 16 k chunks of 64
#define BLK    16384              // one 128row x 128B swizzled block
#define NSTG   3
#define STG_BYTES (4 * BLK)       // Ah|Al|Bh|Bl = 64KB per stage

// ---------------- scratch (device globals: no runtime allocation) ----------
__device__ float g_lat_n[BATCH * NLAT * DIM];                 //   8 MB
__device__ float g_q[BATCH * NLAT * INNER];                   //   8 MB
__device__ float g_kv[(size_t)BATCH * SEQ * 2 * INNER];       // 256 MB (k | v)
__device__ float g_attn[BATCH * NLAT * INNER];                //   8 MB
__device__ uint4 g_A[(size_t)MT * KCH * 2 * BLK / 16];        // 134 MB split-bf16 A
__device__ uint4 g_B[(size_t)NT * KCH * 2 * BLK / 16];        //   8 MB split-bf16 Wt
__device__ uint4 g_qbf[(size_t)BH * 2 * 256 * 128 / 16];      //   8 MB Q hi/lo swizzled
__device__ uint4 g_kbf[(size_t)BH * 64 * 16384 / 16];         // 128 MB K hi/lo (roped)
__device__ uint4 g_vbf[(size_t)BH * 64 * 16384 / 16];         // 128 MB V^T hi/lo

// ---------------- PTX helpers ----------------------------------------------
__device__ __forceinline__ uint32_t smem_u32(const void* p) {
    uint32_t a;
    asm("{ .reg .u64 t; cvta.to.shared.u64 t, %1; cvt.u32.u64 %0, t; }"
        : "=r"(a) : "l"(p));
    return a;
}
__device__ __forceinline__ void mbar_init(uint32_t m, uint32_t cnt) {
    asm volatile("mbarrier.init.shared.b64 [%0], %1;" :: "r"(m), "r"(cnt) : "memory");
}
__device__ __forceinline__ void mbar_expect(uint32_t m, uint32_t bytes) {
    asm volatile("mbarrier.arrive.expect_tx.shared.b64 _, [%0], %1;"
                 :: "r"(m), "r"(bytes) : "memory");
}
__device__ __forceinline__ void mbar_wait(uint32_t m, int ph) {
    asm volatile(
        "{\n\t.reg .pred P;\n\t"
        "W%=:\n\t"
        "mbarrier.try_wait.parity.shared.b64 P, [%0], %1;\n\t"
        "@!P bra W%=;\n\t}"
        :: "r"(m), "r"(ph) : "memory");
}
__device__ __forceinline__ void bulk_g2s(uint32_t dst, const void* src,
                                         uint32_t bytes, uint32_t mbar) {
    asm volatile(
        "cp.async.bulk.shared::cluster.global.mbarrier::complete_tx::bytes "
        "[%0], [%1], %2, [%3];"
        :: "r"(dst), "l"(src), "r"(bytes), "r"(mbar) : "memory");
}
__device__ __forceinline__ void ldmx4(uint32_t* r, uint32_t addr) {
    asm volatile("ldmatrix.sync.aligned.m8n8.x4.shared.b16 {%0,%1,%2,%3}, [%4];"
                 : "=r"(r[0]), "=r"(r[1]), "=r"(r[2]), "=r"(r[3]) : "r"(addr));
}
__device__ __forceinline__ void mma16816(float* c, const uint32_t* a,
                                         uint32_t b0, uint32_t b1) {
    asm volatile(
        "mma.sync.aligned.m16n8k16.row.col.f32.bf16.bf16.f32 "
        "{%0,%1,%2,%3}, {%4,%5,%6,%7}, {%8,%9}, {%0,%1,%2,%3};"
        : "+f"(c[0]), "+f"(c[1]), "+f"(c[2]), "+f"(c[3])
        : "r"(a[0]), "r"(a[1]), "r"(a[2]), "r"(a[3]), "r"(b0), "r"(b1));
}
// split two floats into packed bf16x2 hi and residual lo
__device__ __forceinline__ void split2(float a, float b, uint32_t& hi, uint32_t& lo) {
    __nv_bfloat16 ha = __float2bfloat16(a), hb = __float2bfloat16(b);
    float ra = a - __bfloat162float(ha), rb = b - __bfloat162float(hb);
    __nv_bfloat16 la = __float2bfloat16(ra), lb = __float2bfloat16(rb);
    hi = (uint32_t)__bfloat16_as_ushort(ha) | ((uint32_t)__bfloat16_as_ushort(hb) << 16);
    lo = (uint32_t)__bfloat16_as_ushort(la) | ((uint32_t)__bfloat16_as_ushort(lb) << 16);
}

// ---------------- LayerNorm (fp32 out) for latents --------------------------
__global__ __launch_bounds__(256) void ln_kernel(
    const float* __restrict__ x, const float* __restrict__ gam,
    const float* __restrict__ bet, float* __restrict__ y)
{
    const int row = blockIdx.x;
    const int t = threadIdx.x;
    __shared__ float red[8];

    const float4 v = ((const float4*)(x + (size_t)row * DIM))[t];
    float s = v.x + v.y + v.z + v.w;
    #pragma unroll
    for (int off = 16; off; off >>= 1) s += __shfl_xor_sync(0xffffffffu, s, off);
    if ((t & 31) == 0) red[t >> 5] = s;
    __syncthreads();
    if (t < 8) {
        float r = red[t];
        #pragma unroll
        for (int off = 4; off; off >>= 1) r += __shfl_xor_sync(0xffu, r, off);
        if (t == 0) red[0] = r;
    }
    __syncthreads();
    const float mu = red[0] * (1.0f / DIM);
    const float dx = v.x - mu, dy = v.y - mu, dz = v.z - mu, dw = v.w - mu;
    float s2 = dx * dx + dy * dy + dz * dz + dw * dw;
    __syncthreads();
    #pragma unroll
    for (int off = 16; off; off >>= 1) s2 += __shfl_xor_sync(0xffffffffu, s2, off);
    if ((t & 31) == 0) red[t >> 5] = s2;
    __syncthreads();
    if (t < 8) {
        float r = red[t];
        #pragma unroll
        for (int off = 4; off; off >>= 1) r += __shfl_xor_sync(0xffu, r, off);
        if (t == 0) red[0] = r;
    }
    __syncthreads();
    const float rs = rsqrtf(red[0] * (1.0f / DIM) + EPSLN);

    const float4 gg = ((const float4*)gam)[t];
    const float4 bb = ((const float4*)bet)[t];
    float4 o;
    o.x = dx * rs * gg.x + bb.x;
    o.y = dy * rs * gg.y + bb.y;
    o.z = dz * rs * gg.z + bb.z;
    o.w = dw * rs * gg.w + bb.w;
    ((float4*)(y + (size_t)row * DIM))[t] = o;
}

// -------- LayerNorm for context, fused with split-bf16 tiled/swizzled prep --
__global__ __launch_bounds__(256) void ln_ctx_prep_kernel(
    const float* __restrict__ x, const float* __restrict__ gam,
    const float* __restrict__ bet)
{
    const int row = blockIdx.x;          // m index 0..32767
    const int t = threadIdx.x;
    __shared__ float red[8];

    const float4 v = ((const float4*)(x + (size_t)row * DIM))[t];
    float s = v.x + v.y + v.z + v.w;
    #pragma unroll
    for (int off = 16; off; off >>= 1) s += __shfl_xor_sync(0xffffffffu, s, off);
    if ((t & 31) == 0) red[t >> 5] = s;
    __syncthreads();
    if (t < 8) {
        float r = red[t];
        #pragma unroll
        for (int off = 4; off; off >>= 1) r += __shfl_xor_sync(0xffu, r, off);
        if (t == 0) red[0] = r;
    }
    __syncthreads();
    const float mu = red[0] * (1.0f / DIM);
    const float dx = v.x - mu, dy = v.y - mu, dz = v.z - mu, dw = v.w - mu;
    float s2 = dx * dx + dy * dy + dz * dz + dw * dw;
    __syncthreads();
    #pragma unroll
    for (int off = 16; off; off >>= 1) s2 += __shfl_xor_sync(0xffffffffu, s2, off);
    if ((t & 31) == 0) red[t >> 5] = s2;
    __syncthreads();
    if (t < 8) {
        float r = red[t];
        #pragma unroll
        for (int off = 4; off; off >>= 1) r += __shfl_xor_sync(0xffu, r, off);
        if (t == 0) red[0] = r;
    }
    __syncthreads();
    const float rs = rsqrtf(red[0] * (1.0f / DIM) + EPSLN);

    const float4 gg = ((const float4*)gam)[t];
    const float4 bb = ((const float4*)bet)[t];
    const float o0 = dx * rs * gg.x + bb.x;
    const float o1 = dy * rs * gg.y + bb.y;
    const float o2 = dz * rs * gg.z + bb.z;
    const float o3 = dw * rs * gg.w + bb.w;

    uint32_t h0, l0, h1, l1;
    split2(o0, o1, h0, l0);
    split2(o2, o3, h1, l1);

    const int mt = row >> 7, r = row & 127;
    const int chunk = t >> 4;            // k chunk (64 elems)
    const int c = (t & 15) * 4;          // col within chunk
    uint32_t bo = (uint32_t)(r * 128 + c * 2);
    uint32_t sw = bo ^ ((bo >> 3) & 0x70);
    char* dst = (char*)g_A + ((size_t)(mt * KCH + chunk) * 2) * BLK + sw;
    *(uint2*)dst = make_uint2(h0, h1);
    *(uint2*)(dst + BLK) = make_uint2(l0, l1);
}

// -------- Wkv -> split-bf16, transposed to K-major, tiled/swizzled ----------
__global__ __launch_bounds__(256) void bprep_kernel(const float* __restrict__ Wkv)
{
    const int idx = blockIdx.x * 256 + threadIdx.x;   // k*2048 + n
    const int n = idx & (GN - 1);
    const int k = idx >> 11;
    const float wv = Wkv[idx];
    __nv_bfloat16 h = __float2bfloat16(wv);
    __nv_bfloat16 l = __float2bfloat16(wv - __bfloat162float(h));
    const int nt = n >> 7, r = n & 127, chunk = k >> 6, c = k & 63;
    uint32_t bo = (uint32_t)(r * 128 + c * 2);
    uint32_t sw = bo ^ ((bo >> 3) & 0x70);
    char* dst = (char*)g_B + ((size_t)(nt * KCH + chunk) * 2) * BLK + sw;
    *(unsigned short*)dst = __bfloat16_as_ushort(h);
    *(unsigned short*)(dst + BLK) = __bfloat16_as_ushort(l);
}

// -------- kv GEMM: mma.sync bf16 split, 128x128 tile, 3-stage pipeline ------
#define OFF_FULL 0
#define OFF_STG  1024

extern __shared__ char kv_smem[];
__global__ __launch_bounds__(256) void kv_mma_kernel()
{
    const uint32_t sb = smem_u32(kv_smem);
    const int t = threadIdx.x;
    const int w = t >> 5, lane = t & 31;
    const int bx = blockIdx.x, by = blockIdx.y;
    const int wm = w & 3, wn = w >> 2;          // 4 x 2 warp grid
    const int g = lane >> 2, tig = lane & 3;

    if (t == 0) {
        #pragma unroll
        for (int i = 0; i < NSTG; i++) mbar_init(sb + OFF_FULL + 8 * i, 1);
    }
    __syncthreads();
    asm volatile("fence.proxy.async.shared::cta;" ::: "memory");

    const char* Ab = (const char*)g_A + (size_t)by * KCH * 2 * BLK;
    const char* Bb = (const char*)g_B + (size_t)bx * KCH * 2 * BLK;

    if (t == 0) {
        #pragma unroll
        for (int c = 0; c < NSTG; c++) {
            uint32_t st = sb + OFF_STG + c * STG_BYTES;
            mbar_expect(sb + OFF_FULL + 8 * c, STG_BYTES);
            bulk_g2s(st,           Ab + (size_t)c * 2 * BLK, 2 * BLK, sb + OFF_FULL + 8 * c);
            bulk_g2s(st + 2 * BLK, Bb + (size_t)c * 2 * BLK, 2 * BLK, sb + OFF_FULL + 8 * c);
        }
    }

    const int l15 = lane & 15;
    const uint32_t kb16 = (uint32_t)(lane & 16);
    const uint32_t mask = (uint32_t)((lane & 7) << 4);
    uint32_t aoff[2], boff[4];
    #pragma unroll
    for (int mi = 0; mi < 2; mi++) aoff[mi] = (uint32_t)((wm * 32 + mi * 16 + l15) * 128);
    #pragma unroll
    for (int p = 0; p < 4; p++)    boff[p]  = (uint32_t)((wn * 64 + p * 16 + l15) * 128);

    float acc[2][8][4];
    #pragma unroll
    for (int mi = 0; mi < 2; mi++)
        #pragma unroll
        for (int ni = 0; ni < 8; ni++)
            #pragma unroll
            for (int q = 0; q < 4; q++) acc[mi][ni][q] = 0.f;

    int ph[NSTG] = {0, 0, 0};

    for (int kc = 0; kc < KCH; kc++) {
        const int s = kc % NSTG;
        mbar_wait(sb + OFF_FULL + 8 * s, ph[s]); ph[s] ^= 1;
        const uint32_t base = sb + OFF_STG + s * STG_BYTES;

        #pragma unroll
        for (int ks = 0; ks < 4; ks++) {
            const uint32_t kx = ((uint32_t)(ks * 32) + kb16) ^ mask;
            uint32_t ah[2][4], al[2][4], bh[4][4], bl[4][4];
            #pragma unroll
            for (int mi = 0; mi < 2; mi++) {
                ldmx4(ah[mi], base + aoff[mi] + kx);
                ldmx4(al[mi], base + BLK + aoff[mi] + kx);
            }
            #pragma unroll
            for (int p = 0; p < 4; p++) {
                ldmx4(bh[p], base + 2 * BLK + boff[p] + kx);
                ldmx4(bl[p], base + 3 * BLK + boff[p] + kx);
            }
            #pragma unroll
            for (int mi = 0; mi < 2; mi++)
                #pragma unroll
                for (int p = 0; p < 4; p++) {
                    mma16816(acc[mi][2 * p + 0], ah[mi], bh[p][0], bh[p][2]);
                    mma16816(acc[mi][2 * p + 1], ah[mi], bh[p][1], bh[p][3]);
                    mma16816(acc[mi][2 * p + 0], ah[mi], bl[p][0], bl[p][2]);
                    mma16816(acc[mi][2 * p + 1], ah[mi], bl[p][1], bl[p][3]);
                    mma16816(acc[mi][2 * p + 0], al[mi], bh[p][0], bh[p][2]);
                    mma16816(acc[mi][2 * p + 1], al[mi], bh[p][1], bh[p][3]);
                }
        }
        __syncthreads();
        const int nxt = kc + NSTG;
        if (t == 0 && nxt < KCH) {
            mbar_expect(sb + OFF_FULL + 8 * s, STG_BYTES);
            bulk_g2s(base,           Ab + (size_t)nxt * 2 * BLK, 2 * BLK, sb + OFF_FULL + 8 * s);
            bulk_g2s(base + 2 * BLK, Bb + (size_t)nxt * 2 * BLK, 2 * BLK, sb + OFF_FULL + 8 * s);
        }
    }

    #pragma unroll
    for (int mi = 0; mi < 2; mi++) {
        const int row0 = by * 128 + wm * 32 + mi * 16 + g;
        #pragma unroll
        for (int ni = 0; ni < 8; ni++) {
            const int col = bx * 128 + wn * 64 + ni * 8 + tig * 2;
            *(float2*)&g_kv[(size_t)row0 * GN + col] =
                make_float2(acc[mi][ni][0], acc[mi][ni][1]);
            *(float2*)&g_kv[(size_t)(row0 + 8) * GN + col] =
                make_float2(acc[mi][ni][2], acc[mi][ni][3]);
        }
    }
}

// ---------------- SGEMM 128x128x8 (q and output projections) ---------------
template <bool BIAS>
__global__ __launch_bounds__(256) void sgemm128(
    const float* __restrict__ A, const float* __restrict__ Bm,
    const float* __restrict__ bias, float* __restrict__ C,
    int M, int N, int K)
{
    __shared__ float As[8][128];
    __shared__ float Bs[8][128];

    const int tid = threadIdx.x;
    const int tx = tid & 15, ty = tid >> 4;
    const int bx = blockIdx.x, by = blockIdx.y;

    const int arow = tid >> 1,  acol = (tid & 1) * 4;
    const int brow = tid >> 5,  bcol = (tid & 31) * 4;
    const float* Aptr = A + (size_t)(by * 128 + arow) * K + acol;
    const float* Bptr = Bm + (size_t)brow * N + bx * 128 + bcol;

    float acc[8][8];
    #pragma unroll
    for (int i = 0; i < 8; i++)
        #pragma unroll
        for (int j = 0; j < 8; j++) acc[i][j] = 0.f;

    for (int k0 = 0; k0 < K; k0 += 8) {
        const float4 av = *(const float4*)(Aptr + k0);
        const float4 bv = *(const float4*)(Bptr + (size_t)k0 * N);
        As[acol + 0][arow] = av.x;
        As[acol + 1][arow] = av.y;
        As[acol + 2][arow] = av.z;
        As[acol + 3][arow] = av.w;
        *(float4*)&Bs[brow][bcol] = bv;
        __syncthreads();

        #pragma unroll
        for (int kk = 0; kk < 8; kk++) {
            const float4 a0 = *(float4*)&As[kk][ty * 4];
            const float4 a1 = *(float4*)&As[kk][64 + ty * 4];
            const float4 b0 = *(float4*)&Bs[kk][tx * 4];
            const float4 b1 = *(float4*)&Bs[kk][64 + tx * 4];
            const float a[8] = {a0.x, a0.y, a0.z, a0.w, a1.x, a1.y, a1.z, a1.w};
            const float b[8] = {b0.x, b0.y, b0.z, b0.w, b1.x, b1.y, b1.z, b1.w};
            #pragma unroll
            for (int i = 0; i < 8; i++)
                #pragma unroll
                for (int j = 0; j < 8; j++) acc[i][j] += a[i] * b[j];
        }
        __syncthreads();
    }

    #pragma unroll
    for (int ih = 0; ih < 2; ih++)
        #pragma unroll
        for (int i = 0; i < 4; i++) {
            const int row = by * 128 + ih * 64 + ty * 4 + i;
            #pragma unroll
            for (int jh = 0; jh < 2; jh++) {
                const int col = bx * 128 + jh * 64 + tx * 4;
                float4 v;
                v.x = acc[ih * 4 + i][jh * 4 + 0];
                v.y = acc[ih * 4 + i][jh * 4 + 1];
                v.z = acc[ih * 4 + i][jh * 4 + 2];
                v.w = acc[ih * 4 + i][jh * 4 + 3];
                if (BIAS) {
                    v.x += bias[col + 0];
                    v.y += bias[col + 1];
                    v.z += bias[col + 2];
                    v.w += bias[col + 3];
                }
                *(float4*)&C[(size_t)row * N + col] = v;
            }
        }
}

// -------- q -> split-bf16 swizzled per-head layout --------------------------
__global__ __launch_bounds__(256) void qconv_kernel()
{
    const int idx = blockIdx.x * 256 + threadIdx.x;
    const int d4 = idx & 15;
    const int h = (idx >> 4) & 15;
    const int row = idx >> 8;         // b*256+n
    const int b = row >> 8, n = row & 255;
    const float4 v = *(const float4*)&g_q[(size_t)row * INNER + h * 64 + d4 * 4];
    uint32_t h0, l0, h1, l1;
    split2(v.x, v.y, h0, l0);
    split2(v.z, v.w, h1, l1);
    const int bh = b * 16 + h;
    uint32_t bo = (uint32_t)(n * 128 + d4 * 8);
    uint32_t sw = bo ^ ((bo >> 3) & 0x70);
    char* base = (char*)g_qbf + (size_t)bh * 65536;
    *(uint2*)(base + sw) = make_uint2(h0, h1);
    *(uint2*)(base + 32768 + sw) = make_uint2(l0, l1);
}

// -------- k: RoPE fused + split-bf16 swizzled chunked layout ----------------
__global__ __launch_bounds__(256) void kconv_kernel(
    const float* __restrict__ cosb, const float* __restrict__ sinb)
{
    const int idx = blockIdx.x * 256 + threadIdx.x;   // over B*S*H*16
    const int j = idx & 15;           // d-pair index: d = 2j
    const int h = (idx >> 4) & 15;
    const int s = (idx >> 8) & 4095;
    const int b = idx >> 20;
    const float* src = &g_kv[((size_t)(b * SEQ + s)) * GN + h * 64];
    const float2 k1 = *(const float2*)(src + 2 * j);
    const float2 k2 = *(const float2*)(src + 2 * j + 32);
    const float2 c  = *(const float2*)&cosb[s * 32 + 2 * j];
    const float2 sn = *(const float2*)&sinb[s * 32 + 2 * j];
    const float lo0 = k1.x * c.x - k2.x * sn.x;
    const float lo1 = k1.y * c.y - k2.y * sn.y;
    const float hi0 = k2.x * c.x + k1.x * sn.x;
    const float hi1 = k2.y * c.y + k1.y * sn.y;
    uint32_t ph, pl, qh, ql;
    split2(lo0, lo1, ph, pl);
    split2(hi0, hi1, qh, ql);
    char* dst = (char*)g_kbf + ((size_t)((b * 16 + h) * 64 + (s >> 6))) * 16384;
    const int r = s & 63;
    uint32_t bo1 = (uint32_t)(r * 128 + 4 * j);
    uint32_t bo2 = bo1 + 64;
    uint32_t sw1 = bo1 ^ ((bo1 >> 3) & 0x70);
    uint32_t sw2 = bo2 ^ ((bo2 >> 3) & 0x70);
    *(uint32_t*)(dst + sw1) = ph;
    *(uint32_t*)(dst + sw2) = qh;
    *(uint32_t*)(dst + 8192 + sw1) = pl;
    *(uint32_t*)(dst + 8192 + sw2) = ql;
}

// -------- v: transpose (smem) + split-bf16 swizzled [d][s] chunks -----------
__global__ __launch_bounds__(256) void vconv_kernel()
{
    __shared__ float ts[64][68];      // pitch 68 floats = 272B: 16B-aligned rows
    const int blk = blockIdx.x;       // bh*64 + sc
    const int bh = blk >> 6, sc = blk & 63;
    const int b = bh >> 4, h = bh & 15;
    const int t = threadIdx.x;
    {
        const int s = t >> 2, dq = (t & 3) * 16;
        const float* src =
            &g_kv[((size_t)(b * SEQ + sc * 64 + s)) * GN + INNER + h * 64 + dq];
        #pragma unroll
        for (int i = 0; i < 4; i++)
            *(float4*)&ts[s][dq + 4 * i] = *(const float4*)(src + 4 * i);
    }
    __syncthreads();
    {
        const int d = t >> 2, sq = (t & 3) * 16;
        char* dst = (char*)g_vbf + ((size_t)bh * 64 + sc) * 16384;
        uint32_t hi[8], lo[8];
        #pragma unroll
        for (int jj = 0; jj < 8; jj++)
            split2(ts[sq + 2 * jj][d], ts[sq + 2 * jj + 1][d], hi[jj], lo[jj]);
        uint32_t bo = (uint32_t)(d * 128 + sq * 2);
        uint32_t sw1 = bo ^ ((bo >> 3) & 0x70);
        uint32_t bo2 = bo + 16;
        uint32_t sw2 = bo2 ^ ((bo2 >> 3) & 0x70);
        *(uint4*)(dst + sw1) = make_uint4(hi[0], hi[1], hi[2], hi[3]);
        *(uint4*)(dst + sw2) = make_uint4(hi[4], hi[5], hi[6], hi[7]);
        *(uint4*)(dst + 8192 + sw1) = make_uint4(lo[0], lo[1], lo[2], lo[3]);
        *(uint4*)(dst + 8192 + sw2) = make_uint4(lo[4], lo[5], lo[6], lo[7]);
    }
}

// -------- Flash attention on tensor cores (split-bf16 3-pass) ---------------
#define ACH 32768      // per stage: K(hi|lo 16KB) + V(hi|lo 16KB)

extern __shared__ char at_smem[];
__global__ __launch_bounds__(256) void attn_mma_kernel()
{
    const uint32_t sb = smem_u32(at_smem);
    const int t = threadIdx.x, w = t >> 5, lane = t & 31;
    const int bh = blockIdx.y;
    const int b = bh >> 4, h = bh & 15;
    const int n0 = blockIdx.x * 128;
    const int g = lane >> 2, tig = lane & 3;
    const int l15 = lane & 15;
    const uint32_t kb16 = (uint32_t)(lane & 16);
    const uint32_t mask = (uint32_t)((lane & 7) << 4);
    const uint32_t stg = sb + 64;

    if (t == 0) { mbar_init(sb, 1); mbar_init(sb + 8, 1); }
    __syncthreads();
    asm volatile("fence.proxy.async.shared::cta;" ::: "memory");

    // Q tile (hi|lo, rows n0..n0+127) -> stage0, then to registers
    const char* Qg = (const char*)g_qbf + (size_t)bh * 65536 + (size_t)n0 * 128;
    if (t == 0) {
        mbar_expect(sb, 32768);
        bulk_g2s(stg,         Qg,         16384, sb);
        bulk_g2s(stg + 16384, Qg + 32768, 16384, sb);
    }
    mbar_wait(sb, 0);

    uint32_t aqh[4][4], aql[4][4];
    #pragma unroll
    for (int ks = 0; ks < 4; ks++) {
        const uint32_t kx = ((uint32_t)(ks * 32) + kb16) ^ mask;
        const uint32_t ro = (uint32_t)((w * 16 + l15) * 128);
        ldmx4(aqh[ks], stg + ro + kx);
        ldmx4(aql[ks], stg + 16384 + ro + kx);
    }
    __syncthreads();

    // prime 2-stage KV pipeline
    const char* Kg = (const char*)g_kbf + (size_t)bh * 64 * 16384;
    const char* Vg = (const char*)g_vbf + (size_t)bh * 64 * 16384;
    if (t == 0) {
        #pragma unroll
        for (int c = 0; c < 2; c++) {
            mbar_expect(sb + 8 * c, 32768);
            bulk_g2s(stg + c * ACH,         Kg + (size_t)c * 16384, 16384, sb + 8 * c);
            bulk_g2s(stg + c * ACH + 16384, Vg + (size_t)c * 16384, 16384, sb + 8 * c);
        }
    }
    int ph0 = 1, ph1 = 0;   // full0 already consumed once (Q load)

    float mA = -1e30f, mB = -1e30f, lA = 0.f, lB = 0.f;
    float o[8][4];
    #pragma unroll
    for (int ni = 0; ni < 8; ni++)
        #pragma unroll
        for (int q = 0; q < 4; q++) o[ni][q] = 0.f;

    for (int sc = 0; sc < 64; sc++) {
        const int s = sc & 1;
        if (s == 0) { mbar_wait(sb, ph0); ph0 ^= 1; }
        else        { mbar_wait(sb + 8, ph1); ph1 ^= 1; }
        const uint32_t kb = stg + s * ACH;
        const uint32_t vb = kb + 16384;

        // S = Q K^T (3-pass split-bf16)
        float sacc[8][4];
        #pragma unroll
        for (int ni = 0; ni < 8; ni++)
            #pragma unroll
            for (int q = 0; q < 4; q++) sacc[ni][q] = 0.f;

        #pragma unroll
        for (int ks = 0; ks < 4; ks++) {
            const uint32_t kx = ((uint32_t)(ks * 32) + kb16) ^ mask;
            #pragma unroll
            for (int p = 0; p < 4; p++) {
                uint32_t kh[4], kl[4];
                const uint32_t ro = (uint32_t)((p * 16 + l15) * 128);
                ldmx4(kh, kb + ro + kx);
                ldmx4(kl, kb + 8192 + ro + kx);
                mma16816(sacc[2 * p + 0], aqh[ks], kh[0], kh[2]);
                mma16816(sacc[2 * p + 1], aqh[ks], kh[1], kh[3]);
                mma16816(sacc[2 * p + 0], aqh[ks], kl[0], kl[2]);
                mma16816(sacc[2 * p + 1], aqh[ks], kl[1], kl[3]);
                mma16816(sacc[2 * p + 0], aql[ks], kh[0], kh[2]);
                mma16816(sacc[2 * p + 1], aql[ks], kh[1], kh[3]);
            }
        }

        // scale + clip + online softmax (rows: A = c0/c1, B = c2/c3)
        float mlA = -1e30f, mlB = -1e30f;
        #pragma unroll
        for (int ni = 0; ni < 8; ni++) {
            sacc[ni][0] = fminf(11.f, fmaxf(-11.f, sacc[ni][0] * 0.125f));
            sacc[ni][1] = fminf(11.f, fmaxf(-11.f, sacc[ni][1] * 0.125f));
            sacc[ni][2] = fminf(11.f, fmaxf(-11.f, sacc[ni][2] * 0.125f));
            sacc[ni][3] = fminf(11.f, fmaxf(-11.f, sacc[ni][3] * 0.125f));
            mlA = fmaxf(mlA, fmaxf(sacc[ni][0], sacc[ni][1]));
            mlB = fmaxf(mlB, fmaxf(sacc[ni][2], sacc[ni][3]));
        }
        mlA = fmaxf(mlA, __shfl_xor_sync(0xffffffffu, mlA, 1));
        mlA = fmaxf(mlA, __shfl_xor_sync(0xffffffffu, mlA, 2));
        mlB = fmaxf(mlB, __shfl_xor_sync(0xffffffffu, mlB, 1));
        mlB = fmaxf(mlB, __shfl_xor_sync(0xffffffffu, mlB, 2));
        const float mnA = fmaxf(mA, mlA), mnB = fmaxf(mB, mlB);
        const float cA = __expf(mA - mnA), cB = __expf(mB - mnB);
        float psA = 0.f, psB = 0.f;
        #pragma unroll
        for (int ni = 0; ni < 8; ni++) {
            sacc[ni][0] = __expf(sacc[ni][0] - mnA); psA += sacc[ni][0];
            sacc[ni][1] = __expf(sacc[ni][1] - mnA); psA += sacc[ni][1];
            sacc[ni][2] = __expf(sacc[ni][2] - mnB); psB += sacc[ni][2];
            sacc[ni][3] = __expf(sacc[ni][3] - mnB); psB += sacc[ni][3];
        }
        psA += __shfl_xor_sync(0xffffffffu, psA, 1);
        psA += __shfl_xor_sync(0xffffffffu, psA, 2);
        psB += __shfl_xor_sync(0xffffffffu, psB, 1);
        psB += __shfl_xor_sync(0xffffffffu, psB, 2);
        lA = lA * cA + psA; mA = mnA;
        lB = lB * cB + psB; mB = mnB;
        #pragma unroll
        for (int ni = 0; ni < 8; ni++) {
            o[ni][0] *= cA; o[ni][1] *= cA;
            o[ni][2] *= cB; o[ni][3] *= cB;
        }

        // O += P V (3-pass; P fragments packed from sacc in A-operand order)
        #pragma unroll
        for (int ks = 0; ks < 4; ks++) {
            uint32_t pah[4], pal[4];
            split2(sacc[2 * ks][0],     sacc[2 * ks][1],     pah[0], pal[0]);
            split2(sacc[2 * ks][2],     sacc[2 * ks][3],     pah[1], pal[1]);
            split2(sacc[2 * ks + 1][0], sacc[2 * ks + 1][1], pah[2], pal[2]);
            split2(sacc[2 * ks + 1][2], sacc[2 * ks + 1][3], pah[3], pal[3]);
            const uint32_t kx = ((uint32_t)(ks * 32) + kb16) ^ mask;
            #pragma unroll
            for (int p = 0; p < 4; p++) {
                uint32_t vh[4], vl[4];
                const uint32_t ro = (uint32_t)((p * 16 + l15) * 128);
                ldmx4(vh, vb + ro + kx);
                ldmx4(vl, vb + 8192 + ro + kx);
                mma16816(o[2 * p + 0], pah, vh[0], vh[2]);
                mma16816(o[2 * p + 1], pah, vh[1], vh[3]);
                mma16816(o[2 * p + 0], pah, vl[0], vl[2]);
                mma16816(o[2 * p + 1], pah, vl[1], vl[3]);
                mma16816(o[2 * p + 0], pal, vh[0], vh[2]);
                mma16816(o[2 * p + 1], pal, vh[1], vh[3]);
            }
        }
        __syncthreads();
        if (t == 0 && sc + 2 < 64) {
            const int nc = sc + 2;
            const uint32_t dst = stg + s * ACH;
            mbar_expect(sb + 8 * s, 32768);
            bulk_g2s(dst,         Kg + (size_t)nc * 16384, 16384, sb + 8 * s);
            bulk_g2s(dst + 16384, Vg + (size_t)nc * 16384, 16384, sb + 8 * s);
        }
    }

    // finalize
    const float iA = 1.f / lA, iB = 1.f / lB;
    const size_t rA = ((size_t)(b * NLAT + n0 + w * 16 + g)) * INNER + h * 64;
    const size_t rB = rA + 8 * INNER;
    #pragma unroll
    for (int ni = 0; ni < 8; ni++) {
        *(float2*)&g_attn[rA + ni * 8 + tig * 2] =
            make_float2(o[ni][0] * iA, o[ni][1] * iA);
        *(float2*)&g_attn[rB + ni * 8 + tig * 2] =
            make_float2(o[ni][2] * iB, o[ni][3] * iB);
    }
}

// ---------------- host launcher --------------------------------------------
extern "C" void kernel_launch(void* const* d_in, const int* in_sizes, int n_in,
                              void* d_out, int out_size)
{
    const float* latents  = (const float*)d_in[0];
    const float* context  = (const float*)d_in[1];
    const float* cosb     = (const float*)d_in[2];
    const float* sinb     = (const float*)d_in[3];
    const float* ln_lat_g = (const float*)d_in[4];
    const float* ln_lat_b = (const float*)d_in[5];
    const float* ln_ctx_g = (const float*)d_in[6];
    const float* ln_ctx_b = (const float*)d_in[7];
    const float* Wq       = (const float*)d_in[8];
    const float* Wkv      = (const float*)d_in[9];
    const float* Wo       = (const float*)d_in[10];
    const float* bo       = (const float*)d_in[11];
    float* out = (float*)d_out;

    float *lat_n, *q, *attn;
    cudaGetSymbolAddress((void**)&lat_n, g_lat_n);
    cudaGetSymbolAddress((void**)&q,     g_q);
    cudaGetSymbolAddress((void**)&attn,  g_attn);

    // 1. LayerNorms (+ split-bf16 prep for kv GEMM)
    ln_kernel<<<BATCH * NLAT, 256>>>(latents, ln_lat_g, ln_lat_b, lat_n);
    ln_ctx_prep_kernel<<<BATCH * SEQ, 256>>>(context, ln_ctx_g, ln_ctx_b);
    bprep_kernel<<<(DIM * GN) / 256, 256>>>(Wkv);

    // 2. q projection + conversion to bf16 operand layout
    sgemm128<false><<<dim3(INNER / 128, (BATCH * NLAT) / 128), 256>>>(
        lat_n, Wq, nullptr, q, BATCH * NLAT, INNER, DIM);
    qconv_kernel<<<(BATCH * NLAT * 256) / 256, 256>>>();

    // 3. kv projection on tensor cores
    const int kv_smem_bytes = OFF_STG + NSTG * STG_BYTES;   // 197632
    cudaFuncSetAttribute(kv_mma_kernel, cudaFuncAttributeMaxDynamicSharedMemorySize,
                         kv_smem_bytes);
    kv_mma_kernel<<<dim3(NT, MT), 256, kv_smem_bytes>>>();

    // 4. k: RoPE + bf16 convert; v: transpose + bf16 convert
    kconv_kernel<<<(BATCH * SEQ * HEADS * 16) / 256, 256>>>(cosb, sinb);
    vconv_kernel<<<BH * 64, 256>>>();

    // 5. attention on tensor cores
    const int at_smem_bytes = 64 + 2 * ACH;   // 65600
    cudaFuncSetAttribute(attn_mma_kernel, cudaFuncAttributeMaxDynamicSharedMemorySize,
                         at_smem_bytes);
    attn_mma_kernel<<<dim3(NLAT / 128, BH), 256, at_smem_bytes>>>();

    // 6. output projection + bias
    sgemm128<true><<<dim3(DIM / 128, (BATCH * NLAT) / 128), 256>>>(
        attn, Wo, bo, out, BATCH * NLAT, DIM, INNER);
}

// round 11
// speedup vs baseline: 4.2159x; 1.1312x over previous
#include <cuda_runtime.h>
#include <cuda_bf16.h>
#include <math.h>
#include <stdint.h>

#define BATCH 8
#define NLAT  256
#define SEQ   4096
#define DIM   1024
#define HEADS 16
#define DHEAD 64
#define INNER 1024
#define EPSLN 1e-5f
#define BH    (BATCH * HEADS)     // 128

// ---- GEMM geometry
#define GM     (BATCH * SEQ)      // 32768
#define GN     (2 * INNER)        // 2048
#define MT     (GM / 128)         // 256 m tiles (kv)
#define NT     (GN / 128)         // 16 n tiles (kv)
#define KCH    (DIM / 64)         // 16 k chunks of 64
#define BLK    16384              // one 128row x 128B swizzled block
#define NSTG   3
#define STG_BYTES (4 * BLK)       // Ah|Al|Bh|Bl = 64KB per stage
#define OFF_STG  1024

// ---------------- scratch (device globals: no runtime allocation) ----------
__device__ float g_kv[(size_t)BATCH * SEQ * 2 * INNER];       // 256 MB (k | v)
__device__ uint4 g_A[(size_t)MT * KCH * 2 * BLK / 16];        // 134 MB ctx split-bf16
__device__ uint4 g_B[(size_t)NT * KCH * 2 * BLK / 16];        //   8 MB Wkv split
__device__ uint4 g_Aq[(size_t)16 * KCH * 2 * BLK / 16];       //   8 MB lat split
__device__ uint4 g_Bq[(size_t)8 * KCH * 2 * BLK / 16];        //   4 MB Wq split
__device__ uint4 g_Bo[(size_t)8 * KCH * 2 * BLK / 16];        //   4 MB Wo split
__device__ uint4 g_obf[(size_t)16 * KCH * 2 * BLK / 16];      //   8 MB attn-out split
__device__ uint4 g_qbf[(size_t)BH * 2 * 256 * 128 / 16];      //   8 MB Q hi/lo swizzled
__device__ uint4 g_kbf[(size_t)BH * 64 * 16384 / 16];         // 128 MB K hi/lo (roped)
__device__ uint4 g_vbf[(size_t)BH * 64 * 16384 / 16];         // 128 MB V^T hi/lo

// ---------------- PTX helpers ----------------------------------------------
__device__ __forceinline__ uint32_t smem_u32(const void* p) {
    uint32_t a;
    asm("{ .reg .u64 t; cvta.to.shared.u64 t, %1; cvt.u32.u64 %0, t; }"
        : "=r"(a) : "l"(p));
    return a;
}
__device__ __forceinline__ void mbar_init(uint32_t m, uint32_t cnt) {
    asm volatile("mbarrier.init.shared.b64 [%0], %1;" :: "r"(m), "r"(cnt) : "memory");
}
__device__ __forceinline__ void mbar_expect(uint32_t m, uint32_t bytes) {
    asm volatile("mbarrier.arrive.expect_tx.shared.b64 _, [%0], %1;"
                 :: "r"(m), "r"(bytes) : "memory");
}
__device__ __forceinline__ void mbar_wait(uint32_t m, int ph) {
    asm volatile(
        "{\n\t.reg .pred P;\n\t"
        "W%=:\n\t"
        "mbarrier.try_wait.parity.shared.b64 P, [%0], %1;\n\t"
        "@!P bra W%=;\n\t}"
        :: "r"(m), "r"(ph) : "memory");
}
__device__ __forceinline__ void bulk_g2s(uint32_t dst, const void* src,
                                         uint32_t bytes, uint32_t mbar) {
    asm volatile(
        "cp.async.bulk.shared::cluster.global.mbarrier::complete_tx::bytes "
        "[%0], [%1], %2, [%3];"
        :: "r"(dst), "l"(src), "r"(bytes), "r"(mbar) : "memory");
}
__device__ __forceinline__ void ldmx4(uint32_t* r, uint32_t addr) {
    asm volatile("ldmatrix.sync.aligned.m8n8.x4.shared.b16 {%0,%1,%2,%3}, [%4];"
                 : "=r"(r[0]), "=r"(r[1]), "=r"(r[2]), "=r"(r[3]) : "r"(addr));
}
__device__ __forceinline__ void mma16816(float* c, const uint32_t* a,
                                         uint32_t b0, uint32_t b1) {
    asm volatile(
        "mma.sync.aligned.m16n8k16.row.col.f32.bf16.bf16.f32 "
        "{%0,%1,%2,%3}, {%4,%5,%6,%7}, {%8,%9}, {%0,%1,%2,%3};"
        : "+f"(c[0]), "+f"(c[1]), "+f"(c[2]), "+f"(c[3])
        : "r"(a[0]), "r"(a[1]), "r"(a[2]), "r"(a[3]), "r"(b0), "r"(b1));
}
__device__ __forceinline__ void split2(float a, float b, uint32_t& hi, uint32_t& lo) {
    __nv_bfloat16 ha = __float2bfloat16(a), hb = __float2bfloat16(b);
    float ra = a - __bfloat162float(ha), rb = b - __bfloat162float(hb);
    __nv_bfloat16 la = __float2bfloat16(ra), lb = __float2bfloat16(rb);
    hi = (uint32_t)__bfloat16_as_ushort(ha) | ((uint32_t)__bfloat16_as_ushort(hb) << 16);
    lo = (uint32_t)__bfloat16_as_ushort(la) | ((uint32_t)__bfloat16_as_ushort(lb) << 16);
}

// ---------------- shared split-bf16 mma mainloop ----------------------------
// A tile: 128 rows x (kch*64) cols; B tile: 128 rows x (kch*64) cols, both in
// chunked [chunk][hi|lo][16KB swizzled] layout. acc covers 128x128 output.
__device__ __forceinline__ void mma_tile_mainloop(
    const char* __restrict__ Ab, const char* __restrict__ Bb, const int kch,
    const uint32_t sb, float (&acc)[2][8][4])
{
    const int t = threadIdx.x;
    const int w = t >> 5, lane = t & 31;
    const int wm = w & 3, wn = w >> 2;          // 4 x 2 warp grid

    if (t == 0) {
        #pragma unroll
        for (int i = 0; i < NSTG; i++) mbar_init(sb + 8 * i, 1);
    }
    __syncthreads();
    asm volatile("fence.proxy.async.shared::cta;" ::: "memory");

    if (t == 0) {
        #pragma unroll
        for (int c = 0; c < NSTG; c++) {
            uint32_t st = sb + OFF_STG + c * STG_BYTES;
            mbar_expect(sb + 8 * c, STG_BYTES);
            bulk_g2s(st,           Ab + (size_t)c * 2 * BLK, 2 * BLK, sb + 8 * c);
            bulk_g2s(st + 2 * BLK, Bb + (size_t)c * 2 * BLK, 2 * BLK, sb + 8 * c);
        }
    }

    const int l15 = lane & 15;
    const uint32_t kb16 = (uint32_t)(lane & 16);
    const uint32_t mask = (uint32_t)((lane & 7) << 4);
    uint32_t aoff[2], boff[4];
    #pragma unroll
    for (int mi = 0; mi < 2; mi++) aoff[mi] = (uint32_t)((wm * 32 + mi * 16 + l15) * 128);
    #pragma unroll
    for (int p = 0; p < 4; p++)    boff[p]  = (uint32_t)((wn * 64 + p * 16 + l15) * 128);

    #pragma unroll
    for (int mi = 0; mi < 2; mi++)
        #pragma unroll
        for (int ni = 0; ni < 8; ni++)
            #pragma unroll
            for (int q = 0; q < 4; q++) acc[mi][ni][q] = 0.f;

    int ph[NSTG] = {0, 0, 0};

    for (int kc = 0; kc < kch; kc++) {
        const int s = kc % NSTG;
        mbar_wait(sb + 8 * s, ph[s]); ph[s] ^= 1;
        const uint32_t base = sb + OFF_STG + s * STG_BYTES;

        #pragma unroll
        for (int ks = 0; ks < 4; ks++) {
            const uint32_t kx = ((uint32_t)(ks * 32) + kb16) ^ mask;
            uint32_t ah[2][4], al[2][4], bh[4][4], bl[4][4];
            #pragma unroll
            for (int mi = 0; mi < 2; mi++) {
                ldmx4(ah[mi], base + aoff[mi] + kx);
                ldmx4(al[mi], base + BLK + aoff[mi] + kx);
            }
            #pragma unroll
            for (int p = 0; p < 4; p++) {
                ldmx4(bh[p], base + 2 * BLK + boff[p] + kx);
                ldmx4(bl[p], base + 3 * BLK + boff[p] + kx);
            }
            #pragma unroll
            for (int mi = 0; mi < 2; mi++)
                #pragma unroll
                for (int p = 0; p < 4; p++) {
                    mma16816(acc[mi][2 * p + 0], ah[mi], bh[p][0], bh[p][2]);
                    mma16816(acc[mi][2 * p + 1], ah[mi], bh[p][1], bh[p][3]);
                    mma16816(acc[mi][2 * p + 0], ah[mi], bl[p][0], bl[p][2]);
                    mma16816(acc[mi][2 * p + 1], ah[mi], bl[p][1], bl[p][3]);
                    mma16816(acc[mi][2 * p + 0], al[mi], bh[p][0], bh[p][2]);
                    mma16816(acc[mi][2 * p + 1], al[mi], bh[p][1], bh[p][3]);
                }
        }
        __syncthreads();
        const int nxt = kc + NSTG;
        if (t == 0 && nxt < kch) {
            mbar_expect(sb + 8 * s, STG_BYTES);
            bulk_g2s(base,           Ab + (size_t)nxt * 2 * BLK, 2 * BLK, sb + 8 * s);
            bulk_g2s(base + 2 * BLK, Bb + (size_t)nxt * 2 * BLK, 2 * BLK, sb + 8 * s);
        }
    }
}

// -------- LayerNorm fused with split-bf16 tiled/swizzled A-prep -------------
__global__ __launch_bounds__(256) void ln_prep_kernel(
    const float* __restrict__ x, const float* __restrict__ gam,
    const float* __restrict__ bet, uint4* __restrict__ dstb)
{
    const int row = blockIdx.x;
    const int t = threadIdx.x;
    __shared__ float red[8];

    const float4 v = ((const float4*)(x + (size_t)row * DIM))[t];
    float s = v.x + v.y + v.z + v.w;
    #pragma unroll
    for (int off = 16; off; off >>= 1) s += __shfl_xor_sync(0xffffffffu, s, off);
    if ((t & 31) == 0) red[t >> 5] = s;
    __syncthreads();
    if (t < 8) {
        float r = red[t];
        #pragma unroll
        for (int off = 4; off; off >>= 1) r += __shfl_xor_sync(0xffu, r, off);
        if (t == 0) red[0] = r;
    }
    __syncthreads();
    const float mu = red[0] * (1.0f / DIM);
    const float dx = v.x - mu, dy = v.y - mu, dz = v.z - mu, dw = v.w - mu;
    float s2 = dx * dx + dy * dy + dz * dz + dw * dw;
    __syncthreads();
    #pragma unroll
    for (int off = 16; off; off >>= 1) s2 += __shfl_xor_sync(0xffffffffu, s2, off);
    if ((t & 31) == 0) red[t >> 5] = s2;
    __syncthreads();
    if (t < 8) {
        float r = red[t];
        #pragma unroll
        for (int off = 4; off; off >>= 1) r += __shfl_xor_sync(0xffu, r, off);
        if (t == 0) red[0] = r;
    }
    __syncthreads();
    const float rs = rsqrtf(red[0] * (1.0f / DIM) + EPSLN);

    const float4 gg = ((const float4*)gam)[t];
    const float4 bb = ((const float4*)bet)[t];
    const float o0 = dx * rs * gg.x + bb.x;
    const float o1 = dy * rs * gg.y + bb.y;
    const float o2 = dz * rs * gg.z + bb.z;
    const float o3 = dw * rs * gg.w + bb.w;

    uint32_t h0, l0, h1, l1;
    split2(o0, o1, h0, l0);
    split2(o2, o3, h1, l1);

    const int mt = row >> 7, r = row & 127;
    const int chunk = t >> 4;            // k chunk (64 elems)
    const int c = (t & 15) * 4;          // col within chunk
    uint32_t bo = (uint32_t)(r * 128 + c * 2);
    uint32_t sw = bo ^ ((bo >> 3) & 0x70);
    char* dst = (char*)dstb + ((size_t)(mt * KCH + chunk) * 2) * BLK + sw;
    *(uint2*)dst = make_uint2(h0, h1);
    *(uint2*)(dst + BLK) = make_uint2(l0, l1);
}

// -------- weight [K=1024, N] -> split-bf16 K-major tiled/swizzled -----------
__global__ __launch_bounds__(256) void wprep_kernel(
    const float* __restrict__ W, uint4* __restrict__ dstb, int nbits)
{
    const int idx = blockIdx.x * 256 + threadIdx.x;   // k*N + n
    const int n = idx & ((1 << nbits) - 1);
    const int k = idx >> nbits;
    const float wv = W[idx];
    __nv_bfloat16 h = __float2bfloat16(wv);
    __nv_bfloat16 l = __float2bfloat16(wv - __bfloat162float(h));
    const int nt = n >> 7, r = n & 127, chunk = k >> 6, c = k & 63;
    uint32_t bo = (uint32_t)(r * 128 + c * 2);
    uint32_t sw = bo ^ ((bo >> 3) & 0x70);
    char* dst = (char*)dstb + ((size_t)(nt * KCH + chunk) * 2) * BLK + sw;
    *(unsigned short*)dst = __bfloat16_as_ushort(h);
    *(unsigned short*)(dst + BLK) = __bfloat16_as_ushort(l);
}

// -------- kv GEMM: epilogue -> fp32 g_kv ------------------------------------
extern __shared__ char dyn_smem[];
__global__ __launch_bounds__(256) void kv_mma_kernel()
{
    const uint32_t sb = smem_u32(dyn_smem);
    const int t = threadIdx.x, w = t >> 5, lane = t & 31;
    const int wm = w & 3, wn = w >> 2, g = lane >> 2, tig = lane & 3;
    const int bx = blockIdx.x, by = blockIdx.y;

    float acc[2][8][4];
    mma_tile_mainloop((const char*)g_A + (size_t)by * KCH * 2 * BLK,
                      (const char*)g_B + (size_t)bx * KCH * 2 * BLK, KCH, sb, acc);

    #pragma unroll
    for (int mi = 0; mi < 2; mi++) {
        const int row0 = by * 128 + wm * 32 + mi * 16 + g;
        #pragma unroll
        for (int ni = 0; ni < 8; ni++) {
            const int col = bx * 128 + wn * 64 + ni * 8 + tig * 2;
            *(float2*)&g_kv[(size_t)row0 * GN + col] =
                make_float2(acc[mi][ni][0], acc[mi][ni][1]);
            *(float2*)&g_kv[(size_t)(row0 + 8) * GN + col] =
                make_float2(acc[mi][ni][2], acc[mi][ni][3]);
        }
    }
}

// -------- q GEMM: epilogue -> g_qbf (split-bf16 per-head swizzled) ----------
__global__ __launch_bounds__(256) void q_mma_kernel()
{
    const uint32_t sb = smem_u32(dyn_smem);
    const int t = threadIdx.x, w = t >> 5, lane = t & 31;
    const int wm = w & 3, wn = w >> 2, g = lane >> 2, tig = lane & 3;
    const int bx = blockIdx.x, by = blockIdx.y;   // bx 0..7, by 0..15

    float acc[2][8][4];
    mma_tile_mainloop((const char*)g_Aq + (size_t)by * KCH * 2 * BLK,
                      (const char*)g_Bq + (size_t)bx * KCH * 2 * BLK, KCH, sb, acc);

    const int h = bx * 2 + wn;
    #pragma unroll
    for (int mi = 0; mi < 2; mi++) {
        const int grow = by * 128 + wm * 32 + mi * 16 + g;
        const int b = grow >> 8, n = grow & 255;
        char* base = (char*)g_qbf + (size_t)(b * 16 + h) * 65536;
        #pragma unroll
        for (int ni = 0; ni < 8; ni++) {
            uint32_t hi, lo;
            split2(acc[mi][ni][0], acc[mi][ni][1], hi, lo);
            uint32_t bo = (uint32_t)(n * 128 + 16 * ni + 4 * tig);
            uint32_t sw = bo ^ ((bo >> 3) & 0x70);
            *(uint32_t*)(base + sw) = hi;
            *(uint32_t*)(base + 32768 + sw) = lo;
            split2(acc[mi][ni][2], acc[mi][ni][3], hi, lo);
            uint32_t bo2 = (uint32_t)((n + 8) * 128 + 16 * ni + 4 * tig);
            uint32_t sw2 = bo2 ^ ((bo2 >> 3) & 0x70);
            *(uint32_t*)(base + sw2) = hi;
            *(uint32_t*)(base + 32768 + sw2) = lo;
        }
    }
}

// -------- o GEMM: A = g_obf (attn out), epilogue -> out fp32 + bias ---------
__global__ __launch_bounds__(256) void o_mma_kernel(
    const float* __restrict__ bias, float* __restrict__ out)
{
    const uint32_t sb = smem_u32(dyn_smem);
    const int t = threadIdx.x, w = t >> 5, lane = t & 31;
    const int wm = w & 3, wn = w >> 2, g = lane >> 2, tig = lane & 3;
    const int bx = blockIdx.x, by = blockIdx.y;   // bx 0..7, by 0..15

    float acc[2][8][4];
    mma_tile_mainloop((const char*)g_obf + (size_t)by * KCH * 2 * BLK,
                      (const char*)g_Bo + (size_t)bx * KCH * 2 * BLK, KCH, sb, acc);

    #pragma unroll
    for (int mi = 0; mi < 2; mi++) {
        const int row0 = by * 128 + wm * 32 + mi * 16 + g;
        #pragma unroll
        for (int ni = 0; ni < 8; ni++) {
            const int col = bx * 128 + wn * 64 + ni * 8 + tig * 2;
            const float2 bb = *(const float2*)&bias[col];
            *(float2*)&out[(size_t)row0 * DIM + col] =
                make_float2(acc[mi][ni][0] + bb.x, acc[mi][ni][1] + bb.y);
            *(float2*)&out[(size_t)(row0 + 8) * DIM + col] =
                make_float2(acc[mi][ni][2] + bb.x, acc[mi][ni][3] + bb.y);
        }
    }
}

// -------- k: RoPE fused + split-bf16 swizzled chunked layout ----------------
__global__ __launch_bounds__(256) void kconv_kernel(
    const float* __restrict__ cosb, const float* __restrict__ sinb)
{
    const int idx = blockIdx.x * 256 + threadIdx.x;   // over B*S*H*16
    const int j = idx & 15;           // d-pair index: d = 2j
    const int h = (idx >> 4) & 15;
    const int s = (idx >> 8) & 4095;
    const int b = idx >> 20;
    const float* src = &g_kv[((size_t)(b * SEQ + s)) * GN + h * 64];
    const float2 k1 = *(const float2*)(src + 2 * j);
    const float2 k2 = *(const float2*)(src + 2 * j + 32);
    const float2 c  = *(const float2*)&cosb[s * 32 + 2 * j];
    const float2 sn = *(const float2*)&sinb[s * 32 + 2 * j];
    const float lo0 = k1.x * c.x - k2.x * sn.x;
    const float lo1 = k1.y * c.y - k2.y * sn.y;
    const float hi0 = k2.x * c.x + k1.x * sn.x;
    const float hi1 = k2.y * c.y + k1.y * sn.y;
    uint32_t ph, pl, qh, ql;
    split2(lo0, lo1, ph, pl);
    split2(hi0, hi1, qh, ql);
    char* dst = (char*)g_kbf + ((size_t)((b * 16 + h) * 64 + (s >> 6))) * 16384;
    const int r = s & 63;
    uint32_t bo1 = (uint32_t)(r * 128 + 4 * j);
    uint32_t bo2 = bo1 + 64;
    uint32_t sw1 = bo1 ^ ((bo1 >> 3) & 0x70);
    uint32_t sw2 = bo2 ^ ((bo2 >> 3) & 0x70);
    *(uint32_t*)(dst + sw1) = ph;
    *(uint32_t*)(dst + sw2) = qh;
    *(uint32_t*)(dst + 8192 + sw1) = pl;
    *(uint32_t*)(dst + 8192 + sw2) = ql;
}

// -------- v: transpose (smem) + split-bf16 swizzled [d][s] chunks -----------
__global__ __launch_bounds__(256) void vconv_kernel()
{
    __shared__ float ts[64][68];      // pitch 68 floats: 16B-aligned rows
    const int blk = blockIdx.x;       // bh*64 + sc
    const int bh = blk >> 6, sc = blk & 63;
    const int b = bh >> 4, h = bh & 15;
    const int t = threadIdx.x;
    {
        const int s = t >> 2, dq = (t & 3) * 16;
        const float* src =
            &g_kv[((size_t)(b * SEQ + sc * 64 + s)) * GN + INNER + h * 64 + dq];
        #pragma unroll
        for (int i = 0; i < 4; i++)
            *(float4*)&ts[s][dq + 4 * i] = *(const float4*)(src + 4 * i);
    }
    __syncthreads();
    {
        const int d = t >> 2, sq = (t & 3) * 16;
        char* dst = (char*)g_vbf + ((size_t)bh * 64 + sc) * 16384;
        uint32_t hi[8], lo[8];
        #pragma unroll
        for (int jj = 0; jj < 8; jj++)
            split2(ts[sq + 2 * jj][d], ts[sq + 2 * jj + 1][d], hi[jj], lo[jj]);
        uint32_t bo = (uint32_t)(d * 128 + sq * 2);
        uint32_t sw1 = bo ^ ((bo >> 3) & 0x70);
        uint32_t bo2 = bo + 16;
        uint32_t sw2 = bo2 ^ ((bo2 >> 3) & 0x70);
        *(uint4*)(dst + sw1) = make_uint4(hi[0], hi[1], hi[2], hi[3]);
        *(uint4*)(dst + sw2) = make_uint4(hi[4], hi[5], hi[6], hi[7]);
        *(uint4*)(dst + 8192 + sw1) = make_uint4(lo[0], lo[1], lo[2], lo[3]);
        *(uint4*)(dst + 8192 + sw2) = make_uint4(lo[4], lo[5], lo[6], lo[7]);
    }
}

// -------- Flash attention on tensor cores (split-bf16 3-pass) ---------------
#define ACH 32768      // per stage: K(hi|lo 16KB) + V(hi|lo 16KB)

__global__ __launch_bounds__(256) void attn_mma_kernel()
{
    const uint32_t sb = smem_u32(dyn_smem);
    const int t = threadIdx.x, w = t >> 5, lane = t & 31;
    const int bh = blockIdx.y;
    const int b = bh >> 4, h = bh & 15;
    const int n0 = blockIdx.x * 128;
    const int g = lane >> 2, tig = lane & 3;
    const int l15 = lane & 15;
    const uint32_t kb16 = (uint32_t)(lane & 16);
    const uint32_t mask = (uint32_t)((lane & 7) << 4);
    const uint32_t stg = sb + 64;

    if (t == 0) { mbar_init(sb, 1); mbar_init(sb + 8, 1); }
    __syncthreads();
    asm volatile("fence.proxy.async.shared::cta;" ::: "memory");

    // Q tile (hi|lo, rows n0..n0+127) -> stage0, then to registers
    const char* Qg = (const char*)g_qbf + (size_t)bh * 65536 + (size_t)n0 * 128;
    if (t == 0) {
        mbar_expect(sb, 32768);
        bulk_g2s(stg,         Qg,         16384, sb);
        bulk_g2s(stg + 16384, Qg + 32768, 16384, sb);
    }
    mbar_wait(sb, 0);

    uint32_t aqh[4][4], aql[4][4];
    #pragma unroll
    for (int ks = 0; ks < 4; ks++) {
        const uint32_t kx = ((uint32_t)(ks * 32) + kb16) ^ mask;
        const uint32_t ro = (uint32_t)((w * 16 + l15) * 128);
        ldmx4(aqh[ks], stg + ro + kx);
        ldmx4(aql[ks], stg + 16384 + ro + kx);
    }
    __syncthreads();

    // prime 2-stage KV pipeline
    const char* Kg = (const char*)g_kbf + (size_t)bh * 64 * 16384;
    const char* Vg = (const char*)g_vbf + (size_t)bh * 64 * 16384;
    if (t == 0) {
        #pragma unroll
        for (int c = 0; c < 2; c++) {
            mbar_expect(sb + 8 * c, 32768);
            bulk_g2s(stg + c * ACH,         Kg + (size_t)c * 16384, 16384, sb + 8 * c);
            bulk_g2s(stg + c * ACH + 16384, Vg + (size_t)c * 16384, 16384, sb + 8 * c);
        }
    }
    int ph0 = 1, ph1 = 0;   // full0 already consumed once (Q load)

    float mA = -1e30f, mB = -1e30f, lA = 0.f, lB = 0.f;
    float o[8][4];
    #pragma unroll
    for (int ni = 0; ni < 8; ni++)
        #pragma unroll
        for (int q = 0; q < 4; q++) o[ni][q] = 0.f;

    for (int sc = 0; sc < 64; sc++) {
        const int s = sc & 1;
        if (s == 0) { mbar_wait(sb, ph0); ph0 ^= 1; }
        else        { mbar_wait(sb + 8, ph1); ph1 ^= 1; }
        const uint32_t kb = stg + s * ACH;
        const uint32_t vb = kb + 16384;

        // S = Q K^T (3-pass split-bf16)
        float sacc[8][4];
        #pragma unroll
        for (int ni = 0; ni < 8; ni++)
            #pragma unroll
            for (int q = 0; q < 4; q++) sacc[ni][q] = 0.f;

        #pragma unroll
        for (int ks = 0; ks < 4; ks++) {
            const uint32_t kx = ((uint32_t)(ks * 32) + kb16) ^ mask;
            #pragma unroll
            for (int p = 0; p < 4; p++) {
                uint32_t kh[4], kl[4];
                const uint32_t ro = (uint32_t)((p * 16 + l15) * 128);
                ldmx4(kh, kb + ro + kx);
                ldmx4(kl, kb + 8192 + ro + kx);
                mma16816(sacc[2 * p + 0], aqh[ks], kh[0], kh[2]);
                mma16816(sacc[2 * p + 1], aqh[ks], kh[1], kh[3]);
                mma16816(sacc[2 * p + 0], aqh[ks], kl[0], kl[2]);
                mma16816(sacc[2 * p + 1], aqh[ks], kl[1], kl[3]);
                mma16816(sacc[2 * p + 0], aql[ks], kh[0], kh[2]);
                mma16816(sacc[2 * p + 1], aql[ks], kh[1], kh[3]);
            }
        }

        // scale + clip + online softmax (rows: A = c0/c1, B = c2/c3)
        float mlA = -1e30f, mlB = -1e30f;
        #pragma unroll
        for (int ni = 0; ni < 8; ni++) {
            sacc[ni][0] = fminf(11.f, fmaxf(-11.f, sacc[ni][0] * 0.125f));
            sacc[ni][1] = fminf(11.f, fmaxf(-11.f, sacc[ni][1] * 0.125f));
            sacc[ni][2] = fminf(11.f, fmaxf(-11.f, sacc[ni][2] * 0.125f));
            sacc[ni][3] = fminf(11.f, fmaxf(-11.f, sacc[ni][3] * 0.125f));
            mlA = fmaxf(mlA, fmaxf(sacc[ni][0], sacc[ni][1]));
            mlB = fmaxf(mlB, fmaxf(sacc[ni][2], sacc[ni][3]));
        }
        mlA = fmaxf(mlA, __shfl_xor_sync(0xffffffffu, mlA, 1));
        mlA = fmaxf(mlA, __shfl_xor_sync(0xffffffffu, mlA, 2));
        mlB = fmaxf(mlB, __shfl_xor_sync(0xffffffffu, mlB, 1));
        mlB = fmaxf(mlB, __shfl_xor_sync(0xffffffffu, mlB, 2));
        const float mnA = fmaxf(mA, mlA), mnB = fmaxf(mB, mlB);
        const float cA = __expf(mA - mnA), cB = __expf(mB - mnB);
        float psA = 0.f, psB = 0.f;
        #pragma unroll
        for (int ni = 0; ni < 8; ni++) {
            sacc[ni][0] = __expf(sacc[ni][0] - mnA); psA += sacc[ni][0];
            sacc[ni][1] = __expf(sacc[ni][1] - mnA); psA += sacc[ni][1];
            sacc[ni][2] = __expf(sacc[ni][2] - mnB); psB += sacc[ni][2];
            sacc[ni][3] = __expf(sacc[ni][3] - mnB); psB += sacc[ni][3];
        }
        psA += __shfl_xor_sync(0xffffffffu, psA, 1);
        psA += __shfl_xor_sync(0xffffffffu, psA, 2);
        psB += __shfl_xor_sync(0xffffffffu, psB, 1);
        psB += __shfl_xor_sync(0xffffffffu, psB, 2);
        lA = lA * cA + psA; mA = mnA;
        lB = lB * cB + psB; mB = mnB;
        #pragma unroll
        for (int ni = 0; ni < 8; ni++) {
            o[ni][0] *= cA; o[ni][1] *= cA;
            o[ni][2] *= cB; o[ni][3] *= cB;
        }

        // O += P V (3-pass; P fragments packed from sacc in A-operand order)
        #pragma unroll
        for (int ks = 0; ks < 4; ks++) {
            uint32_t pah[4], pal[4];
            split2(sacc[2 * ks][0],     sacc[2 * ks][1],     pah[0], pal[0]);
            split2(sacc[2 * ks][2],     sacc[2 * ks][3],     pah[1], pal[1]);
            split2(sacc[2 * ks + 1][0], sacc[2 * ks + 1][1], pah[2], pal[2]);
            split2(sacc[2 * ks + 1][2], sacc[2 * ks + 1][3], pah[3], pal[3]);
            const uint32_t kx = ((uint32_t)(ks * 32) + kb16) ^ mask;
            #pragma unroll
            for (int p = 0; p < 4; p++) {
                uint32_t vh[4], vl[4];
                const uint32_t ro = (uint32_t)((p * 16 + l15) * 128);
                ldmx4(vh, vb + ro + kx);
                ldmx4(vl, vb + 8192 + ro + kx);
                mma16816(o[2 * p + 0], pah, vh[0], vh[2]);
                mma16816(o[2 * p + 1], pah, vh[1], vh[3]);
                mma16816(o[2 * p + 0], pah, vl[0], vl[2]);
                mma16816(o[2 * p + 1], pah, vl[1], vl[3]);
                mma16816(o[2 * p + 0], pal, vh[0], vh[2]);
                mma16816(o[2 * p + 1], pal, vh[1], vh[3]);
            }
        }
        __syncthreads();
        if (t == 0 && sc + 2 < 64) {
            const int nc = sc + 2;
            const uint32_t dst = stg + s * ACH;
            mbar_expect(sb + 8 * s, 32768);
            bulk_g2s(dst,         Kg + (size_t)nc * 16384, 16384, sb + 8 * s);
            bulk_g2s(dst + 16384, Vg + (size_t)nc * 16384, 16384, sb + 8 * s);
        }
    }

    // finalize: write split-bf16 into g_obf (A-operand layout for o_mma).
    // row (of 2048) = b*256 + n0 + w*16 + g (+8); chunk = h; byte = r*128 + 2d
    const float iA = 1.f / lA, iB = 1.f / lB;
    const int growA = b * NLAT + n0 + w * 16 + g;       // +8 stays in same tile
    const int mt = growA >> 7;
    char* ob = (char*)g_obf + ((size_t)(mt * KCH + h) * 2) * BLK;
    const int rA = growA & 127;
    #pragma unroll
    for (int ni = 0; ni < 8; ni++) {
        uint32_t hi, lo;
        split2(o[ni][0] * iA, o[ni][1] * iA, hi, lo);
        uint32_t bo = (uint32_t)(rA * 128 + 16 * ni + 4 * tig);
        uint32_t sw = bo ^ ((bo >> 3) & 0x70);
        *(uint32_t*)(ob + sw) = hi;
        *(uint32_t*)(ob + BLK + sw) = lo;
        split2(o[ni][2] * iB, o[ni][3] * iB, hi, lo);
        uint32_t bo2 = (uint32_t)((rA + 8) * 128 + 16 * ni + 4 * tig);
        uint32_t sw2 = bo2 ^ ((bo2 >> 3) & 0x70);
        *(uint32_t*)(ob + sw2) = hi;
        *(uint32_t*)(ob + BLK + sw2) = lo;
    }
}

// ---------------- host launcher --------------------------------------------
extern "C" void kernel_launch(void* const* d_in, const int* in_sizes, int n_in,
                              void* d_out, int out_size)
{
    const float* latents  = (const float*)d_in[0];
    const float* context  = (const float*)d_in[1];
    const float* cosb     = (const float*)d_in[2];
    const float* sinb     = (const float*)d_in[3];
    const float* ln_lat_g = (const float*)d_in[4];
    const float* ln_lat_b = (const float*)d_in[5];
    const float* ln_ctx_g = (const float*)d_in[6];
    const float* ln_ctx_b = (const float*)d_in[7];
    const float* Wq       = (const float*)d_in[8];
    const float* Wkv      = (const float*)d_in[9];
    const float* Wo       = (const float*)d_in[10];
    const float* bo       = (const float*)d_in[11];
    float* out = (float*)d_out;

    uint4 *pAq, *pA, *pBq, *pB, *pBo;
    cudaGetSymbolAddress((void**)&pAq, g_Aq);
    cudaGetSymbolAddress((void**)&pA,  g_A);
    cudaGetSymbolAddress((void**)&pBq, g_Bq);
    cudaGetSymbolAddress((void**)&pB,  g_B);
    cudaGetSymbolAddress((void**)&pBo, g_Bo);

    const int gemm_smem = OFF_STG + NSTG * STG_BYTES;   // 197632
    cudaFuncSetAttribute(kv_mma_kernel, cudaFuncAttributeMaxDynamicSharedMemorySize, gemm_smem);
    cudaFuncSetAttribute(q_mma_kernel,  cudaFuncAttributeMaxDynamicSharedMemorySize, gemm_smem);
    cudaFuncSetAttribute(o_mma_kernel,  cudaFuncAttributeMaxDynamicSharedMemorySize, gemm_smem);
    const int at_smem_bytes = 64 + 2 * ACH;   // 65600
    cudaFuncSetAttribute(attn_mma_kernel, cudaFuncAttributeMaxDynamicSharedMemorySize, at_smem_bytes);

    // 1. LayerNorms fused with split-bf16 A-prep
    ln_prep_kernel<<<BATCH * NLAT, 256>>>(latents, ln_lat_g, ln_lat_b, pAq);
    ln_prep_kernel<<<BATCH * SEQ,  256>>>(context, ln_ctx_g, ln_ctx_b, pA);

    // 2. weight preps
    wprep_kernel<<<(DIM * INNER) / 256, 256>>>(Wq,  pBq, 10);
    wprep_kernel<<<(DIM * GN)    / 256, 256>>>(Wkv, pB,  11);
    wprep_kernel<<<(INNER * DIM) / 256, 256>>>(Wo,  pBo, 10);

    // 3. q projection -> g_qbf directly
    q_mma_kernel<<<dim3(8, 16), 256, gemm_smem>>>();

    // 4. kv projection -> fp32 g_kv
    kv_mma_kernel<<<dim3(NT, MT), 256, gemm_smem>>>();

    // 5. k: RoPE + bf16 convert; v: transpose + bf16 convert
    kconv_kernel<<<(BATCH * SEQ * HEADS * 16) / 256, 256>>>(cosb, sinb);
    vconv_kernel<<<BH * 64, 256>>>();

    // 6. attention -> g_obf (split-bf16 o-proj operand)
    attn_mma_kernel<<<dim3(NLAT / 128, BH), 256, at_smem_bytes>>>();

    // 7. output projection + bias -> out
    o_mma_kernel<<<dim3(8, 16), 256, gemm_smem>>>(bo, out);
}

// round 12
// speedup vs baseline: 4.4659x; 1.0593x over previous
#include <cuda_runtime.h>
#include <cuda_bf16.h>
#include <math.h>
#include <stdint.h>

#define BATCH 8
#define NLAT  256
#define SEQ   4096
#define DIM   1024
#define HEADS 16
#define DHEAD 64
#define INNER 1024
#define EPSLN 1e-5f
#define BH    (BATCH * HEADS)     // 128

// ---- GEMM geometry
#define GM     (BATCH * SEQ)      // 32768
#define GN     (2 * INNER)        // 2048
#define MT     (GM / 128)         // 256 m tiles (kv)
#define NT     (GN / 128)         // 16 n tiles (kv)
#define KCH    (DIM / 64)         // 16 k chunks of 64
#define BLK    16384              // one 128row x 128B swizzled block
#define NSTG   3
#define STG_BYTES (4 * BLK)       // Ah|Al|Bh|Bl = 64KB per stage
#define OFF_STG  1024

// ---------------- scratch (device globals: no runtime allocation) ----------
__device__ uint4 g_A[(size_t)MT * KCH * 2 * BLK / 16];        // 134 MB ctx split-bf16
__device__ uint4 g_B[(size_t)NT * KCH * 2 * BLK / 16];        //   8 MB Wkv split
__device__ uint4 g_Aq[(size_t)16 * KCH * 2 * BLK / 16];       //   8 MB lat split
__device__ uint4 g_Bq[(size_t)8 * KCH * 2 * BLK / 16];        //   4 MB Wq split
__device__ uint4 g_Bo[(size_t)8 * KCH * 2 * BLK / 16];        //   4 MB Wo split
__device__ uint4 g_obf[(size_t)16 * KCH * 2 * BLK / 16];      //   8 MB attn-out split
__device__ uint4 g_qbf[(size_t)BH * 2 * 256 * 128 / 16];      //   8 MB Q hi/lo swizzled
__device__ uint4 g_kbf[(size_t)BH * 64 * 16384 / 16];         // 128 MB K hi/lo (roped)
__device__ uint4 g_vbf[(size_t)BH * 64 * 16384 / 16];         // 128 MB V^T hi/lo

// ---------------- PTX helpers ----------------------------------------------
__device__ __forceinline__ uint32_t smem_u32(const void* p) {
    uint32_t a;
    asm("{ .reg .u64 t; cvta.to.shared.u64 t, %1; cvt.u32.u64 %0, t; }"
        : "=r"(a) : "l"(p));
    return a;
}
__device__ __forceinline__ void mbar_init(uint32_t m, uint32_t cnt) {
    asm volatile("mbarrier.init.shared.b64 [%0], %1;" :: "r"(m), "r"(cnt) : "memory");
}
__device__ __forceinline__ void mbar_expect(uint32_t m, uint32_t bytes) {
    asm volatile("mbarrier.arrive.expect_tx.shared.b64 _, [%0], %1;"
                 :: "r"(m), "r"(bytes) : "memory");
}
__device__ __forceinline__ void mbar_wait(uint32_t m, int ph) {
    asm volatile(
        "{\n\t.reg .pred P;\n\t"
        "W%=:\n\t"
        "mbarrier.try_wait.parity.shared.b64 P, [%0], %1;\n\t"
        "@!P bra W%=;\n\t}"
        :: "r"(m), "r"(ph) : "memory");
}
__device__ __forceinline__ void bulk_g2s(uint32_t dst, const void* src,
                                         uint32_t bytes, uint32_t mbar) {
    asm volatile(
        "cp.async.bulk.shared::cluster.global.mbarrier::complete_tx::bytes "
        "[%0], [%1], %2, [%3];"
        :: "r"(dst), "l"(src), "r"(bytes), "r"(mbar) : "memory");
}
__device__ __forceinline__ void ldmx4(uint32_t* r, uint32_t addr) {
    asm volatile("ldmatrix.sync.aligned.m8n8.x4.shared.b16 {%0,%1,%2,%3}, [%4];"
                 : "=r"(r[0]), "=r"(r[1]), "=r"(r[2]), "=r"(r[3]) : "r"(addr));
}
__device__ __forceinline__ void mma16816(float* c, const uint32_t* a,
                                         uint32_t b0, uint32_t b1) {
    asm volatile(
        "mma.sync.aligned.m16n8k16.row.col.f32.bf16.bf16.f32 "
        "{%0,%1,%2,%3}, {%4,%5,%6,%7}, {%8,%9}, {%0,%1,%2,%3};"
        : "+f"(c[0]), "+f"(c[1]), "+f"(c[2]), "+f"(c[3])
        : "r"(a[0]), "r"(a[1]), "r"(a[2]), "r"(a[3]), "r"(b0), "r"(b1));
}
__device__ __forceinline__ void split2(float a, float b, uint32_t& hi, uint32_t& lo) {
    __nv_bfloat16 ha = __float2bfloat16(a), hb = __float2bfloat16(b);
    float ra = a - __bfloat162float(ha), rb = b - __bfloat162float(hb);
    __nv_bfloat16 la = __float2bfloat16(ra), lb = __float2bfloat16(rb);
    hi = (uint32_t)__bfloat16_as_ushort(ha) | ((uint32_t)__bfloat16_as_ushort(hb) << 16);
    lo = (uint32_t)__bfloat16_as_ushort(la) | ((uint32_t)__bfloat16_as_ushort(lb) << 16);
}

// ---------------- shared split-bf16 mma mainloop ----------------------------
extern __shared__ char dyn_smem[];

__device__ __forceinline__ void mma_tile_mainloop(
    const char* __restrict__ Ab, const char* __restrict__ Bb, const int kch,
    const uint32_t sb, float (&acc)[2][8][4])
{
    const int t = threadIdx.x;
    const int w = t >> 5, lane = t & 31;
    const int wm = w & 3, wn = w >> 2;          // 4 x 2 warp grid

    if (t == 0) {
        #pragma unroll
        for (int i = 0; i < NSTG; i++) mbar_init(sb + 8 * i, 1);
    }
    __syncthreads();
    asm volatile("fence.proxy.async.shared::cta;" ::: "memory");

    if (t == 0) {
        #pragma unroll
        for (int c = 0; c < NSTG; c++) {
            uint32_t st = sb + OFF_STG + c * STG_BYTES;
            mbar_expect(sb + 8 * c, STG_BYTES);
            bulk_g2s(st,           Ab + (size_t)c * 2 * BLK, 2 * BLK, sb + 8 * c);
            bulk_g2s(st + 2 * BLK, Bb + (size_t)c * 2 * BLK, 2 * BLK, sb + 8 * c);
        }
    }

    const int l15 = lane & 15;
    const uint32_t kb16 = (uint32_t)(lane & 16);
    const uint32_t mask = (uint32_t)((lane & 7) << 4);
    uint32_t aoff[2], boff[4];
    #pragma unroll
    for (int mi = 0; mi < 2; mi++) aoff[mi] = (uint32_t)((wm * 32 + mi * 16 + l15) * 128);
    #pragma unroll
    for (int p = 0; p < 4; p++)    boff[p]  = (uint32_t)((wn * 64 + p * 16 + l15) * 128);

    #pragma unroll
    for (int mi = 0; mi < 2; mi++)
        #pragma unroll
        for (int ni = 0; ni < 8; ni++)
            #pragma unroll
            for (int q = 0; q < 4; q++) acc[mi][ni][q] = 0.f;

    int ph[NSTG] = {0, 0, 0};

    for (int kc = 0; kc < kch; kc++) {
        const int s = kc % NSTG;
        mbar_wait(sb + 8 * s, ph[s]); ph[s] ^= 1;
        const uint32_t base = sb + OFF_STG + s * STG_BYTES;

        #pragma unroll
        for (int ks = 0; ks < 4; ks++) {
            const uint32_t kx = ((uint32_t)(ks * 32) + kb16) ^ mask;
            uint32_t ah[2][4], al[2][4], bh[4][4], bl[4][4];
            #pragma unroll
            for (int mi = 0; mi < 2; mi++) {
                ldmx4(ah[mi], base + aoff[mi] + kx);
                ldmx4(al[mi], base + BLK + aoff[mi] + kx);
            }
            #pragma unroll
            for (int p = 0; p < 4; p++) {
                ldmx4(bh[p], base + 2 * BLK + boff[p] + kx);
                ldmx4(bl[p], base + 3 * BLK + boff[p] + kx);
            }
            #pragma unroll
            for (int mi = 0; mi < 2; mi++)
                #pragma unroll
                for (int p = 0; p < 4; p++) {
                    mma16816(acc[mi][2 * p + 0], ah[mi], bh[p][0], bh[p][2]);
                    mma16816(acc[mi][2 * p + 1], ah[mi], bh[p][1], bh[p][3]);
                    mma16816(acc[mi][2 * p + 0], ah[mi], bl[p][0], bl[p][2]);
                    mma16816(acc[mi][2 * p + 1], ah[mi], bl[p][1], bl[p][3]);
                    mma16816(acc[mi][2 * p + 0], al[mi], bh[p][0], bh[p][2]);
                    mma16816(acc[mi][2 * p + 1], al[mi], bh[p][1], bh[p][3]);
                }
        }
        __syncthreads();
        const int nxt = kc + NSTG;
        if (t == 0 && nxt < kch) {
            mbar_expect(sb + 8 * s, STG_BYTES);
            bulk_g2s(base,           Ab + (size_t)nxt * 2 * BLK, 2 * BLK, sb + 8 * s);
            bulk_g2s(base + 2 * BLK, Bb + (size_t)nxt * 2 * BLK, 2 * BLK, sb + 8 * s);
        }
    }
}

// -------- LayerNorm fused with split-bf16 tiled/swizzled A-prep -------------
__global__ __launch_bounds__(256) void ln_prep_kernel(
    const float* __restrict__ x, const float* __restrict__ gam,
    const float* __restrict__ bet, uint4* __restrict__ dstb)
{
    const int row = blockIdx.x;
    const int t = threadIdx.x;
    __shared__ float red[8];

    const float4 v = ((const float4*)(x + (size_t)row * DIM))[t];
    float s = v.x + v.y + v.z + v.w;
    #pragma unroll
    for (int off = 16; off; off >>= 1) s += __shfl_xor_sync(0xffffffffu, s, off);
    if ((t & 31) == 0) red[t >> 5] = s;
    __syncthreads();
    if (t < 8) {
        float r = red[t];
        #pragma unroll
        for (int off = 4; off; off >>= 1) r += __shfl_xor_sync(0xffu, r, off);
        if (t == 0) red[0] = r;
    }
    __syncthreads();
    const float mu = red[0] * (1.0f / DIM);
    const float dx = v.x - mu, dy = v.y - mu, dz = v.z - mu, dw = v.w - mu;
    float s2 = dx * dx + dy * dy + dz * dz + dw * dw;
    __syncthreads();
    #pragma unroll
    for (int off = 16; off; off >>= 1) s2 += __shfl_xor_sync(0xffffffffu, s2, off);
    if ((t & 31) == 0) red[t >> 5] = s2;
    __syncthreads();
    if (t < 8) {
        float r = red[t];
        #pragma unroll
        for (int off = 4; off; off >>= 1) r += __shfl_xor_sync(0xffu, r, off);
        if (t == 0) red[0] = r;
    }
    __syncthreads();
    const float rs = rsqrtf(red[0] * (1.0f / DIM) + EPSLN);

    const float4 gg = ((const float4*)gam)[t];
    const float4 bb = ((const float4*)bet)[t];
    const float o0 = dx * rs * gg.x + bb.x;
    const float o1 = dy * rs * gg.y + bb.y;
    const float o2 = dz * rs * gg.z + bb.z;
    const float o3 = dw * rs * gg.w + bb.w;

    uint32_t h0, l0, h1, l1;
    split2(o0, o1, h0, l0);
    split2(o2, o3, h1, l1);

    const int mt = row >> 7, r = row & 127;
    const int chunk = t >> 4;            // k chunk (64 elems)
    const int c = (t & 15) * 4;          // col within chunk
    uint32_t bo = (uint32_t)(r * 128 + c * 2);
    uint32_t sw = bo ^ ((bo >> 3) & 0x70);
    char* dst = (char*)dstb + ((size_t)(mt * KCH + chunk) * 2) * BLK + sw;
    *(uint2*)dst = make_uint2(h0, h1);
    *(uint2*)(dst + BLK) = make_uint2(l0, l1);
}

// -------- weight [K=1024, N] -> split-bf16 tiled/swizzled (smem transpose) --
__global__ __launch_bounds__(256) void wprep2_kernel(
    const float* __restrict__ W, uint4* __restrict__ dstb, int N)
{
    __shared__ float ws[64][132];     // 132-float pitch: 528B = 33x16, aligned
    const int chunk = blockIdx.x;     // 0..15 (64 k-values each)
    const int nt = blockIdx.y;
    const int t = threadIdx.x;
    {
        const int rr = t >> 5;        // 0..7
        const int cc = (t & 31) * 4;
        #pragma unroll
        for (int i = 0; i < 8; i++) {
            const int k = chunk * 64 + rr + i * 8;
            *(float4*)&ws[rr + i * 8][cc] =
                *(const float4*)&W[(size_t)k * N + nt * 128 + cc];
        }
    }
    __syncthreads();
    const int n = t & 127, sel = t >> 7;
    char* dst = (char*)dstb + ((size_t)(nt * KCH + chunk) * 2) * BLK + sel * BLK;
    #pragma unroll
    for (int j = 0; j < 8; j++) {
        uint32_t outv[4];
        #pragma unroll
        for (int kk = 0; kk < 4; kk++) {
            const int k2 = j * 8 + kk * 2;
            uint32_t hi, lo;
            split2(ws[k2][n], ws[k2 + 1][n], hi, lo);
            outv[kk] = sel ? lo : hi;
        }
        uint32_t bo = (uint32_t)(n * 128 + 16 * j);
        uint32_t sw = bo ^ ((bo >> 3) & 0x70);
        *(uint4*)(dst + sw) = make_uint4(outv[0], outv[1], outv[2], outv[3]);
    }
}

// -------- kv GEMM: fused epilogue -> g_kbf (RoPE) / g_vbf (transpose) -------
__global__ __launch_bounds__(256) void kv_mma_kernel(
    const float* __restrict__ cosb, const float* __restrict__ sinb)
{
    const uint32_t sb = smem_u32(dyn_smem);
    const int t = threadIdx.x, w = t >> 5, lane = t & 31;
    const int wm = w & 3, wn = w >> 2, g = lane >> 2, tig = lane & 3;
    const int bx = blockIdx.x, by = blockIdx.y;

    float acc[2][8][4];
    mma_tile_mainloop((const char*)g_A + (size_t)by * KCH * 2 * BLK,
                      (const char*)g_B + (size_t)bx * KCH * 2 * BLK, KCH, sb, acc);

    if (bx < 8) {
        // ---- K columns: RoPE in registers, write g_kbf swizzled hi/lo ----
        const int h = bx * 2 + wn;
        #pragma unroll
        for (int mi = 0; mi < 2; mi++) {
            const int row0 = by * 128 + wm * 32 + mi * 16 + g;
            const int b = row0 >> 12;
            #pragma unroll
            for (int qq = 0; qq < 2; qq++) {
                const int s = (row0 & 4095) + 8 * qq;
                char* dst = (char*)g_kbf +
                            ((size_t)((b * 16 + h) * 64 + (s >> 6))) * 16384;
                const int r = s & 63;
                const float2* cb  = (const float2*)&cosb[s * 32];
                const float2* sb2 = (const float2*)&sinb[s * 32];
                #pragma unroll
                for (int ni = 0; ni < 4; ni++) {
                    const int d0 = ni * 8 + tig * 2;   // 0..30, partner d0+32
                    const float k1a = acc[mi][ni][2 * qq];
                    const float k1b = acc[mi][ni][2 * qq + 1];
                    const float k2a = acc[mi][ni + 4][2 * qq];
                    const float k2b = acc[mi][ni + 4][2 * qq + 1];
                    const float2 c  = cb[d0 >> 1];
                    const float2 sn = sb2[d0 >> 1];
                    uint32_t hi, lo;
                    split2(k1a * c.x - k2a * sn.x, k1b * c.y - k2b * sn.y, hi, lo);
                    uint32_t bo = (uint32_t)(r * 128 + 2 * d0);
                    uint32_t sw = bo ^ ((bo >> 3) & 0x70);
                    *(uint32_t*)(dst + sw) = hi;
                    *(uint32_t*)(dst + 8192 + sw) = lo;
                    split2(k2a * c.x + k1a * sn.x, k2b * c.y + k1b * sn.y, hi, lo);
                    uint32_t bo2 = bo + 64;            // d0+32
                    uint32_t sw2 = bo2 ^ ((bo2 >> 3) & 0x70);
                    *(uint32_t*)(dst + sw2) = hi;
                    *(uint32_t*)(dst + 8192 + sw2) = lo;
                }
            }
        }
    } else {
        // ---- V columns: smem transpose (stage smem is free) -> g_vbf -------
        unsigned short* VH = (unsigned short*)(dyn_smem + OFF_STG);
        unsigned short* VL = VH + 128 * 136;   // 136-ushort pitch (272B = 17x16)
        #pragma unroll
        for (int mi = 0; mi < 2; mi++)
            #pragma unroll
            for (int ni = 0; ni < 8; ni++)
                #pragma unroll
                for (int q = 0; q < 4; q++) {
                    const int d = wn * 64 + ni * 8 + tig * 2 + (q & 1);
                    const int srow = wm * 32 + mi * 16 + g + 8 * (q >> 1);
                    const float v = acc[mi][ni][q];
                    const __nv_bfloat16 hb = __float2bfloat16(v);
                    const __nv_bfloat16 lb =
                        __float2bfloat16(v - __bfloat162float(hb));
                    VH[d * 136 + srow] = __bfloat16_as_ushort(hb);
                    VL[d * 136 + srow] = __bfloat16_as_ushort(lb);
                }
        __syncthreads();
        const int c = t & 127, sel = t >> 7;
        const int head = (bx - 8) * 2 + (c >> 6);
        const int dd = c & 63;
        const int b = by >> 5;
        const int scb = (by & 31) * 2;
        const unsigned short* src = (sel ? VL : VH) + c * 136;
        #pragma unroll
        for (int blk8 = 0; blk8 < 16; blk8++) {
            const uint4 v = *(const uint4*)(src + blk8 * 8);
            char* dst = (char*)g_vbf +
                        ((size_t)((b * 16 + head) * 64 + scb + (blk8 >> 3))) * 16384 +
                        sel * 8192;
            uint32_t bo = (uint32_t)(dd * 128 + 16 * (blk8 & 7));
            uint32_t sw = bo ^ ((bo >> 3) & 0x70);
            *(uint4*)(dst + sw) = v;
        }
    }
}

// -------- q GEMM: epilogue -> g_qbf (split-bf16 per-head swizzled) ----------
__global__ __launch_bounds__(256) void q_mma_kernel()
{
    const uint32_t sb = smem_u32(dyn_smem);
    const int t = threadIdx.x, w = t >> 5, lane = t & 31;
    const int wm = w & 3, wn = w >> 2, g = lane >> 2, tig = lane & 3;
    const int bx = blockIdx.x, by = blockIdx.y;   // bx 0..7, by 0..15

    float acc[2][8][4];
    mma_tile_mainloop((const char*)g_Aq + (size_t)by * KCH * 2 * BLK,
                      (const char*)g_Bq + (size_t)bx * KCH * 2 * BLK, KCH, sb, acc);

    const int h = bx * 2 + wn;
    #pragma unroll
    for (int mi = 0; mi < 2; mi++) {
        const int grow = by * 128 + wm * 32 + mi * 16 + g;
        const int b = grow >> 8, n = grow & 255;
        char* base = (char*)g_qbf + (size_t)(b * 16 + h) * 65536;
        #pragma unroll
        for (int ni = 0; ni < 8; ni++) {
            uint32_t hi, lo;
            split2(acc[mi][ni][0], acc[mi][ni][1], hi, lo);
            uint32_t bo = (uint32_t)(n * 128 + 16 * ni + 4 * tig);
            uint32_t sw = bo ^ ((bo >> 3) & 0x70);
            *(uint32_t*)(base + sw) = hi;
            *(uint32_t*)(base + 32768 + sw) = lo;
            split2(acc[mi][ni][2], acc[mi][ni][3], hi, lo);
            uint32_t bo2 = (uint32_t)((n + 8) * 128 + 16 * ni + 4 * tig);
            uint32_t sw2 = bo2 ^ ((bo2 >> 3) & 0x70);
            *(uint32_t*)(base + sw2) = hi;
            *(uint32_t*)(base + 32768 + sw2) = lo;
        }
    }
}

// -------- o GEMM: A = g_obf (attn out), epilogue -> out fp32 + bias ---------
__global__ __launch_bounds__(256) void o_mma_kernel(
    const float* __restrict__ bias, float* __restrict__ out)
{
    const uint32_t sb = smem_u32(dyn_smem);
    const int t = threadIdx.x, w = t >> 5, lane = t & 31;
    const int wm = w & 3, wn = w >> 2, g = lane >> 2, tig = lane & 3;
    const int bx = blockIdx.x, by = blockIdx.y;   // bx 0..7, by 0..15

    float acc[2][8][4];
    mma_tile_mainloop((const char*)g_obf + (size_t)by * KCH * 2 * BLK,
                      (const char*)g_Bo + (size_t)bx * KCH * 2 * BLK, KCH, sb, acc);

    #pragma unroll
    for (int mi = 0; mi < 2; mi++) {
        const int row0 = by * 128 + wm * 32 + mi * 16 + g;
        #pragma unroll
        for (int ni = 0; ni < 8; ni++) {
            const int col = bx * 128 + wn * 64 + ni * 8 + tig * 2;
            const float2 bb = *(const float2*)&bias[col];
            *(float2*)&out[(size_t)row0 * DIM + col] =
                make_float2(acc[mi][ni][0] + bb.x, acc[mi][ni][1] + bb.y);
            *(float2*)&out[(size_t)(row0 + 8) * DIM + col] =
                make_float2(acc[mi][ni][2] + bb.x, acc[mi][ni][3] + bb.y);
        }
    }
}

// -------- Flash attention on tensor cores (split-bf16 3-pass) ---------------
#define ACH 32768      // per stage: K(hi|lo 16KB) + V(hi|lo 16KB)

__global__ __launch_bounds__(256) void attn_mma_kernel()
{
    const uint32_t sb = smem_u32(dyn_smem);
    const int t = threadIdx.x, w = t >> 5, lane = t & 31;
    const int bh = blockIdx.y;
    const int b = bh >> 4, h = bh & 15;
    const int n0 = blockIdx.x * 128;
    const int g = lane >> 2, tig = lane & 3;
    const int l15 = lane & 15;
    const uint32_t kb16 = (uint32_t)(lane & 16);
    const uint32_t mask = (uint32_t)((lane & 7) << 4);
    const uint32_t stg = sb + 64;

    if (t == 0) { mbar_init(sb, 1); mbar_init(sb + 8, 1); }
    __syncthreads();
    asm volatile("fence.proxy.async.shared::cta;" ::: "memory");

    const char* Qg = (const char*)g_qbf + (size_t)bh * 65536 + (size_t)n0 * 128;
    if (t == 0) {
        mbar_expect(sb, 32768);
        bulk_g2s(stg,         Qg,         16384, sb);
        bulk_g2s(stg + 16384, Qg + 32768, 16384, sb);
    }
    mbar_wait(sb, 0);

    uint32_t aqh[4][4], aql[4][4];
    #pragma unroll
    for (int ks = 0; ks < 4; ks++) {
        const uint32_t kx = ((uint32_t)(ks * 32) + kb16) ^ mask;
        const uint32_t ro = (uint32_t)((w * 16 + l15) * 128);
        ldmx4(aqh[ks], stg + ro + kx);
        ldmx4(aql[ks], stg + 16384 + ro + kx);
    }
    __syncthreads();

    const char* Kg = (const char*)g_kbf + (size_t)bh * 64 * 16384;
    const char* Vg = (const char*)g_vbf + (size_t)bh * 64 * 16384;
    if (t == 0) {
        #pragma unroll
        for (int c = 0; c < 2; c++) {
            mbar_expect(sb + 8 * c, 32768);
            bulk_g2s(stg + c * ACH,         Kg + (size_t)c * 16384, 16384, sb + 8 * c);
            bulk_g2s(stg + c * ACH + 16384, Vg + (size_t)c * 16384, 16384, sb + 8 * c);
        }
    }
    int ph0 = 1, ph1 = 0;

    float mA = -1e30f, mB = -1e30f, lA = 0.f, lB = 0.f;
    float o[8][4];
    #pragma unroll
    for (int ni = 0; ni < 8; ni++)
        #pragma unroll
        for (int q = 0; q < 4; q++) o[ni][q] = 0.f;

    for (int sc = 0; sc < 64; sc++) {
        const int s = sc & 1;
        if (s == 0) { mbar_wait(sb, ph0); ph0 ^= 1; }
        else        { mbar_wait(sb + 8, ph1); ph1 ^= 1; }
        const uint32_t kb = stg + s * ACH;
        const uint32_t vb = kb + 16384;

        float sacc[8][4];
        #pragma unroll
        for (int ni = 0; ni < 8; ni++)
            #pragma unroll
            for (int q = 0; q < 4; q++) sacc[ni][q] = 0.f;

        #pragma unroll
        for (int ks = 0; ks < 4; ks++) {
            const uint32_t kx = ((uint32_t)(ks * 32) + kb16) ^ mask;
            #pragma unroll
            for (int p = 0; p < 4; p++) {
                uint32_t kh[4], kl[4];
                const uint32_t ro = (uint32_t)((p * 16 + l15) * 128);
                ldmx4(kh, kb + ro + kx);
                ldmx4(kl, kb + 8192 + ro + kx);
                mma16816(sacc[2 * p + 0], aqh[ks], kh[0], kh[2]);
                mma16816(sacc[2 * p + 1], aqh[ks], kh[1], kh[3]);
                mma16816(sacc[2 * p + 0], aqh[ks], kl[0], kl[2]);
                mma16816(sacc[2 * p + 1], aqh[ks], kl[1], kl[3]);
                mma16816(sacc[2 * p + 0], aql[ks], kh[0], kh[2]);
                mma16816(sacc[2 * p + 1], aql[ks], kh[1], kh[3]);
            }
        }

        float mlA = -1e30f, mlB = -1e30f;
        #pragma unroll
        for (int ni = 0; ni < 8; ni++) {
            sacc[ni][0] = fminf(11.f, fmaxf(-11.f, sacc[ni][0] * 0.125f));
            sacc[ni][1] = fminf(11.f, fmaxf(-11.f, sacc[ni][1] * 0.125f));
            sacc[ni][2] = fminf(11.f, fmaxf(-11.f, sacc[ni][2] * 0.125f));
            sacc[ni][3] = fminf(11.f, fmaxf(-11.f, sacc[ni][3] * 0.125f));
            mlA = fmaxf(mlA, fmaxf(sacc[ni][0], sacc[ni][1]));
            mlB = fmaxf(mlB, fmaxf(sacc[ni][2], sacc[ni][3]));
        }
        mlA = fmaxf(mlA, __shfl_xor_sync(0xffffffffu, mlA, 1));
        mlA = fmaxf(mlA, __shfl_xor_sync(0xffffffffu, mlA, 2));
        mlB = fmaxf(mlB, __shfl_xor_sync(0xffffffffu, mlB, 1));
        mlB = fmaxf(mlB, __shfl_xor_sync(0xffffffffu, mlB, 2));
        const float mnA = fmaxf(mA, mlA), mnB = fmaxf(mB, mlB);
        const float cA = __expf(mA - mnA), cB = __expf(mB - mnB);
        float psA = 0.f, psB = 0.f;
        #pragma unroll
        for (int ni = 0; ni < 8; ni++) {
            sacc[ni][0] = __expf(sacc[ni][0] - mnA); psA += sacc[ni][0];
            sacc[ni][1] = __expf(sacc[ni][1] - mnA); psA += sacc[ni][1];
            sacc[ni][2] = __expf(sacc[ni][2] - mnB); psB += sacc[ni][2];
            sacc[ni][3] = __expf(sacc[ni][3] - mnB); psB += sacc[ni][3];
        }
        psA += __shfl_xor_sync(0xffffffffu, psA, 1);
        psA += __shfl_xor_sync(0xffffffffu, psA, 2);
        psB += __shfl_xor_sync(0xffffffffu, psB, 1);
        psB += __shfl_xor_sync(0xffffffffu, psB, 2);
        lA = lA * cA + psA; mA = mnA;
        lB = lB * cB + psB; mB = mnB;
        #pragma unroll
        for (int ni = 0; ni < 8; ni++) {
            o[ni][0] *= cA; o[ni][1] *= cA;
            o[ni][2] *= cB; o[ni][3] *= cB;
        }

        #pragma unroll
        for (int ks = 0; ks < 4; ks++) {
            uint32_t pah[4], pal[4];
            split2(sacc[2 * ks][0],     sacc[2 * ks][1],     pah[0], pal[0]);
            split2(sacc[2 * ks][2],     sacc[2 * ks][3],     pah[1], pal[1]);
            split2(sacc[2 * ks + 1][0], sacc[2 * ks + 1][1], pah[2], pal[2]);
            split2(sacc[2 * ks + 1][2], sacc[2 * ks + 1][3], pah[3], pal[3]);
            const uint32_t kx = ((uint32_t)(ks * 32) + kb16) ^ mask;
            #pragma unroll
            for (int p = 0; p < 4; p++) {
                uint32_t vh[4], vl[4];
                const uint32_t ro = (uint32_t)((p * 16 + l15) * 128);
                ldmx4(vh, vb + ro + kx);
                ldmx4(vl, vb + 8192 + ro + kx);
                mma16816(o[2 * p + 0], pah, vh[0], vh[2]);
                mma16816(o[2 * p + 1], pah, vh[1], vh[3]);
                mma16816(o[2 * p + 0], pah, vl[0], vl[2]);
                mma16816(o[2 * p + 1], pah, vl[1], vl[3]);
                mma16816(o[2 * p + 0], pal, vh[0], vh[2]);
                mma16816(o[2 * p + 1], pal, vh[1], vh[3]);
            }
        }
        __syncthreads();
        if (t == 0 && sc + 2 < 64) {
            const int nc = sc + 2;
            const uint32_t dst = stg + s * ACH;
            mbar_expect(sb + 8 * s, 32768);
            bulk_g2s(dst,         Kg + (size_t)nc * 16384, 16384, sb + 8 * s);
            bulk_g2s(dst + 16384, Vg + (size_t)nc * 16384, 16384, sb + 8 * s);
        }
    }

    // finalize: write split-bf16 into g_obf (A-operand layout for o_mma)
    const float iA = 1.f / lA, iB = 1.f / lB;
    const int growA = b * NLAT + n0 + w * 16 + g;
    const int mt = growA >> 7;
    char* ob = (char*)g_obf + ((size_t)(mt * KCH + h) * 2) * BLK;
    const int rA = growA & 127;
    #pragma unroll
    for (int ni = 0; ni < 8; ni++) {
        uint32_t hi, lo;
        split2(o[ni][0] * iA, o[ni][1] * iA, hi, lo);
        uint32_t bo = (uint32_t)(rA * 128 + 16 * ni + 4 * tig);
        uint32_t sw = bo ^ ((bo >> 3) & 0x70);
        *(uint32_t*)(ob + sw) = hi;
        *(uint32_t*)(ob + BLK + sw) = lo;
        split2(o[ni][2] * iB, o[ni][3] * iB, hi, lo);
        uint32_t bo2 = (uint32_t)((rA + 8) * 128 + 16 * ni + 4 * tig);
        uint32_t sw2 = bo2 ^ ((bo2 >> 3) & 0x70);
        *(uint32_t*)(ob + sw2) = hi;
        *(uint32_t*)(ob + BLK + sw2) = lo;
    }
}

// ---------------- host launcher --------------------------------------------
extern "C" void kernel_launch(void* const* d_in, const int* in_sizes, int n_in,
                              void* d_out, int out_size)
{
    const float* latents  = (const float*)d_in[0];
    const float* context  = (const float*)d_in[1];
    const float* cosb     = (const float*)d_in[2];
    const float* sinb     = (const float*)d_in[3];
    const float* ln_lat_g = (const float*)d_in[4];
    const float* ln_lat_b = (const float*)d_in[5];
    const float* ln_ctx_g = (const float*)d_in[6];
    const float* ln_ctx_b = (const float*)d_in[7];
    const float* Wq       = (const float*)d_in[8];
    const float* Wkv      = (const float*)d_in[9];
    const float* Wo       = (const float*)d_in[10];
    const float* bo       = (const float*)d_in[11];
    float* out = (float*)d_out;

    uint4 *pAq, *pA, *pBq, *pB, *pBo;
    cudaGetSymbolAddress((void**)&pAq, g_Aq);
    cudaGetSymbolAddress((void**)&pA,  g_A);
    cudaGetSymbolAddress((void**)&pBq, g_Bq);
    cudaGetSymbolAddress((void**)&pB,  g_B);
    cudaGetSymbolAddress((void**)&pBo, g_Bo);

    const int gemm_smem = OFF_STG + NSTG * STG_BYTES;   // 197632
    cudaFuncSetAttribute(kv_mma_kernel, cudaFuncAttributeMaxDynamicSharedMemorySize, gemm_smem);
    cudaFuncSetAttribute(q_mma_kernel,  cudaFuncAttributeMaxDynamicSharedMemorySize, gemm_smem);
    cudaFuncSetAttribute(o_mma_kernel,  cudaFuncAttributeMaxDynamicSharedMemorySize, gemm_smem);
    const int at_smem_bytes = 64 + 2 * ACH;   // 65600
    cudaFuncSetAttribute(attn_mma_kernel, cudaFuncAttributeMaxDynamicSharedMemorySize, at_smem_bytes);

    // 1. LayerNorms fused with split-bf16 A-prep
    ln_prep_kernel<<<BATCH * NLAT, 256>>>(latents, ln_lat_g, ln_lat_b, pAq);
    ln_prep_kernel<<<BATCH * SEQ,  256>>>(context, ln_ctx_g, ln_ctx_b, pA);

    // 2. weight preps (smem-tiled, coalesced)
    wprep2_kernel<<<dim3(KCH, 8),  256>>>(Wq,  pBq, INNER);
    wprep2_kernel<<<dim3(KCH, 16), 256>>>(Wkv, pB,  GN);
    wprep2_kernel<<<dim3(KCH, 8),  256>>>(Wo,  pBo, DIM);

    // 3. q projection -> g_qbf directly
    q_mma_kernel<<<dim3(8, 16), 256, gemm_smem>>>();

    // 4. kv projection -> g_kbf (RoPE fused) / g_vbf (transpose fused)
    kv_mma_kernel<<<dim3(NT, MT), 256, gemm_smem>>>(cosb, sinb);

    // 5. attention -> g_obf (split-bf16 o-proj operand)
    attn_mma_kernel<<<dim3(NLAT / 128, BH), 256, at_smem_bytes>>>();

    // 6. output projection + bias -> out
    o_mma_kernel<<<dim3(8, 16), 256, gemm_smem>>>(bo, out);
}

// round 14
// speedup vs baseline: 4.4884x; 1.0050x over previous
#include <cuda_runtime.h>
#include <cuda_bf16.h>
#include <math.h>
#include <stdint.h>

#define BATCH 8
#define NLAT  256
#define SEQ   4096
#define DIM   1024
#define HEADS 16
#define DHEAD 64
#define INNER 1024
#define EPSLN 1e-5f
#define BH    (BATCH * HEADS)     // 128

// ---- GEMM geometry
#define GM     (BATCH * SEQ)      // 32768
#define GN     (2 * INNER)        // 2048
#define MT     (GM / 128)         // 256 m tiles (kv)
#define NT     (GN / 128)         // 16 n tiles (kv)
#define KCH    (DIM / 64)         // 16 k chunks of 64
#define BLK    16384              // one 128row x 128B swizzled block
#define NSTG   3
#define STG_BYTES (4 * BLK)       // Ah|Al|Bh|Bl = 64KB per stage
#define OFF_STG  1024

// ---------------- scratch (device globals: no runtime allocation) ----------
__device__ uint4 g_A[(size_t)MT * KCH * 2 * BLK / 16];        // 134 MB ctx split-bf16
__device__ uint4 g_B[(size_t)NT * KCH * 2 * BLK / 16];        //   8 MB Wkv split
__device__ uint4 g_Aq[(size_t)16 * KCH * 2 * BLK / 16];       //   8 MB lat split
__device__ uint4 g_Bq[(size_t)8 * KCH * 2 * BLK / 16];        //   4 MB Wq split
__device__ uint4 g_Bo[(size_t)8 * KCH * 2 * BLK / 16];        //   4 MB Wo split
__device__ uint4 g_obf[(size_t)16 * KCH * 2 * BLK / 16];      //   8 MB attn-out split
__device__ uint4 g_qbf[(size_t)BH * 2 * 256 * 128 / 16];      //   8 MB Q hi/lo swizzled
__device__ uint4 g_kbf[(size_t)BH * 64 * 16384 / 16];         // 128 MB K hi/lo (roped)
__device__ uint4 g_vbf[(size_t)BH * 64 * 16384 / 16];         // 128 MB V^T hi/lo

// ---------------- PTX helpers ----------------------------------------------
__device__ __forceinline__ uint32_t smem_u32(const void* p) {
    uint32_t a;
    asm("{ .reg .u64 t; cvta.to.shared.u64 t, %1; cvt.u32.u64 %0, t; }"
        : "=r"(a) : "l"(p));
    return a;
}
__device__ __forceinline__ void mbar_init(uint32_t m, uint32_t cnt) {
    asm volatile("mbarrier.init.shared.b64 [%0], %1;" :: "r"(m), "r"(cnt) : "memory");
}
__device__ __forceinline__ void mbar_expect(uint32_t m, uint32_t bytes) {
    asm volatile("mbarrier.arrive.expect_tx.shared.b64 _, [%0], %1;"
                 :: "r"(m), "r"(bytes) : "memory");
}
__device__ __forceinline__ void mbar_wait(uint32_t m, int ph) {
    asm volatile(
        "{\n\t.reg .pred P;\n\t"
        "W%=:\n\t"
        "mbarrier.try_wait.parity.shared.b64 P, [%0], %1;\n\t"
        "@!P bra W%=;\n\t}"
        :: "r"(m), "r"(ph) : "memory");
}
__device__ __forceinline__ void bulk_g2s(uint32_t dst, const void* src,
                                         uint32_t bytes, uint32_t mbar) {
    asm volatile(
        "cp.async.bulk.shared::cluster.global.mbarrier::complete_tx::bytes "
        "[%0], [%1], %2, [%3];"
        :: "r"(dst), "l"(src), "r"(bytes), "r"(mbar) : "memory");
}
__device__ __forceinline__ void ldmx4(uint32_t* r, uint32_t addr) {
    asm volatile("ldmatrix.sync.aligned.m8n8.x4.shared.b16 {%0,%1,%2,%3}, [%4];"
                 : "=r"(r[0]), "=r"(r[1]), "=r"(r[2]), "=r"(r[3]) : "r"(addr));
}
__device__ __forceinline__ void mma16816(float* c, const uint32_t* a,
                                         uint32_t b0, uint32_t b1) {
    asm volatile(
        "mma.sync.aligned.m16n8k16.row.col.f32.bf16.bf16.f32 "
        "{%0,%1,%2,%3}, {%4,%5,%6,%7}, {%8,%9}, {%0,%1,%2,%3};"
        : "+f"(c[0]), "+f"(c[1]), "+f"(c[2]), "+f"(c[3])
        : "r"(a[0]), "r"(a[1]), "r"(a[2]), "r"(a[3]), "r"(b0), "r"(b1));
}
__device__ __forceinline__ void split2(float a, float b, uint32_t& hi, uint32_t& lo) {
    __nv_bfloat16 ha = __float2bfloat16(a), hb = __float2bfloat16(b);
    float ra = a - __bfloat162float(ha), rb = b - __bfloat162float(hb);
    __nv_bfloat16 la = __float2bfloat16(ra), lb = __float2bfloat16(rb);
    hi = (uint32_t)__bfloat16_as_ushort(ha) | ((uint32_t)__bfloat16_as_ushort(hb) << 16);
    lo = (uint32_t)__bfloat16_as_ushort(la) | ((uint32_t)__bfloat16_as_ushort(lb) << 16);
}

// ---------------- shared split-bf16 mma mainloop ----------------------------
extern __shared__ char dyn_smem[];

__device__ __forceinline__ void mma_tile_mainloop(
    const char* __restrict__ Ab, const char* __restrict__ Bb, const int kch,
    const uint32_t sb, float (&acc)[2][8][4])
{
    const int t = threadIdx.x;
    const int w = t >> 5, lane = t & 31;
    const int wm = w & 3, wn = w >> 2;          // 4 x 2 warp grid

    if (t == 0) {
        #pragma unroll
        for (int i = 0; i < NSTG; i++) mbar_init(sb + 8 * i, 1);
    }
    __syncthreads();
    asm volatile("fence.proxy.async.shared::cta;" ::: "memory");

    if (t == 0) {
        #pragma unroll
        for (int c = 0; c < NSTG; c++) {
            uint32_t st = sb + OFF_STG + c * STG_BYTES;
            mbar_expect(sb + 8 * c, STG_BYTES);
            bulk_g2s(st,           Ab + (size_t)c * 2 * BLK, 2 * BLK, sb + 8 * c);
            bulk_g2s(st + 2 * BLK, Bb + (size_t)c * 2 * BLK, 2 * BLK, sb + 8 * c);
        }
    }

    const int l15 = lane & 15;
    const uint32_t kb16 = (uint32_t)(lane & 16);
    const uint32_t mask = (uint32_t)((lane & 7) << 4);
    uint32_t aoff[2], boff[4];
    #pragma unroll
    for (int mi = 0; mi < 2; mi++) aoff[mi] = (uint32_t)((wm * 32 + mi * 16 + l15) * 128);
    #pragma unroll
    for (int p = 0; p < 4; p++)    boff[p]  = (uint32_t)((wn * 64 + p * 16 + l15) * 128);

    #pragma unroll
    for (int mi = 0; mi < 2; mi++)
        #pragma unroll
        for (int ni = 0; ni < 8; ni++)
            #pragma unroll
            for (int q = 0; q < 4; q++) acc[mi][ni][q] = 0.f;

    int ph[NSTG] = {0, 0, 0};

    for (int kc = 0; kc < kch; kc++) {
        const int s = kc % NSTG;
        mbar_wait(sb + 8 * s, ph[s]); ph[s] ^= 1;
        const uint32_t base = sb + OFF_STG + s * STG_BYTES;

        #pragma unroll
        for (int ks = 0; ks < 4; ks++) {
            const uint32_t kx = ((uint32_t)(ks * 32) + kb16) ^ mask;
            uint32_t ah[2][4], al[2][4], bh[4][4], bl[4][4];
            #pragma unroll
            for (int mi = 0; mi < 2; mi++) {
                ldmx4(ah[mi], base + aoff[mi] + kx);
                ldmx4(al[mi], base + BLK + aoff[mi] + kx);
            }
            #pragma unroll
            for (int p = 0; p < 4; p++) {
                ldmx4(bh[p], base + 2 * BLK + boff[p] + kx);
                ldmx4(bl[p], base + 3 * BLK + boff[p] + kx);
            }
            #pragma unroll
            for (int mi = 0; mi < 2; mi++)
                #pragma unroll
                for (int p = 0; p < 4; p++) {
                    mma16816(acc[mi][2 * p + 0], ah[mi], bh[p][0], bh[p][2]);
                    mma16816(acc[mi][2 * p + 1], ah[mi], bh[p][1], bh[p][3]);
                    mma16816(acc[mi][2 * p + 0], ah[mi], bl[p][0], bl[p][2]);
                    mma16816(acc[mi][2 * p + 1], ah[mi], bl[p][1], bl[p][3]);
                    mma16816(acc[mi][2 * p + 0], al[mi], bh[p][0], bh[p][2]);
                    mma16816(acc[mi][2 * p + 1], al[mi], bh[p][1], bh[p][3]);
                }
        }
        __syncthreads();
        const int nxt = kc + NSTG;
        if (t == 0 && nxt < kch) {
            mbar_expect(sb + 8 * s, STG_BYTES);
            bulk_g2s(base,           Ab + (size_t)nxt * 2 * BLK, 2 * BLK, sb + 8 * s);
            bulk_g2s(base + 2 * BLK, Bb + (size_t)nxt * 2 * BLK, 2 * BLK, sb + 8 * s);
        }
    }
}

// -------- LayerNorm (warp-per-row) fused with split-bf16 A-prep -------------
__global__ __launch_bounds__(256) void ln_prep_kernel(
    const float* __restrict__ x, const float* __restrict__ gam,
    const float* __restrict__ bet, uint4* __restrict__ dstb)
{
    const int wid = threadIdx.x >> 5, lane = threadIdx.x & 31;
    const int row = blockIdx.x * 8 + wid;
    const float4* xr = (const float4*)(x + (size_t)row * DIM);

    float4 v[8];
    float s = 0.f;
    #pragma unroll
    for (int i = 0; i < 8; i++) {
        v[i] = xr[i * 32 + lane];
        s += v[i].x + v[i].y + v[i].z + v[i].w;
    }
    #pragma unroll
    for (int off = 16; off; off >>= 1) s += __shfl_xor_sync(0xffffffffu, s, off);
    const float mu = s * (1.0f / DIM);

    float s2 = 0.f;
    #pragma unroll
    for (int i = 0; i < 8; i++) {
        v[i].x -= mu; v[i].y -= mu; v[i].z -= mu; v[i].w -= mu;
        s2 += v[i].x * v[i].x + v[i].y * v[i].y + v[i].z * v[i].z + v[i].w * v[i].w;
    }
    #pragma unroll
    for (int off = 16; off; off >>= 1) s2 += __shfl_xor_sync(0xffffffffu, s2, off);
    const float rs = rsqrtf(s2 * (1.0f / DIM) + EPSLN);

    const int mt = row >> 7, r = row & 127;
    char* dst0 = (char*)dstb + (size_t)(mt * KCH) * 2 * BLK;
    #pragma unroll
    for (int i = 0; i < 8; i++) {
        const int slot = i * 32 + lane;          // float4 slot 0..255
        const float4 gg = ((const float4*)gam)[slot];
        const float4 bb = ((const float4*)bet)[slot];
        const float o0 = v[i].x * rs * gg.x + bb.x;
        const float o1 = v[i].y * rs * gg.y + bb.y;
        const float o2 = v[i].z * rs * gg.z + bb.z;
        const float o3 = v[i].w * rs * gg.w + bb.w;
        uint32_t h0, l0, h1, l1;
        split2(o0, o1, h0, l0);
        split2(o2, o3, h1, l1);
        const int chunk = slot >> 4;
        const int c = (slot & 15) * 4;
        uint32_t bo = (uint32_t)(r * 128 + c * 2);
        uint32_t sw = bo ^ ((bo >> 3) & 0x70);
        char* dst = dst0 + (size_t)chunk * 2 * BLK + sw;
        *(uint2*)dst = make_uint2(h0, h1);
        *(uint2*)(dst + BLK) = make_uint2(l0, l1);
    }
}

// -------- weight [K=1024, N] -> split-bf16 tiled/swizzled (smem transpose) --
__global__ __launch_bounds__(256) void wprep2_kernel(
    const float* __restrict__ W, uint4* __restrict__ dstb, int N)
{
    __shared__ float ws[64][132];     // 132-float pitch: 528B = 33x16, aligned
    const int chunk = blockIdx.x;     // 0..15 (64 k-values each)
    const int nt = blockIdx.y;
    const int t = threadIdx.x;
    {
        const int rr = t >> 5;        // 0..7
        const int cc = (t & 31) * 4;
        #pragma unroll
        for (int i = 0; i < 8; i++) {
            const int k = chunk * 64 + rr + i * 8;
            *(float4*)&ws[rr + i * 8][cc] =
                *(const float4*)&W[(size_t)k * N + nt * 128 + cc];
        }
    }
    __syncthreads();
    const int n = t & 127, sel = t >> 7;
    char* dst = (char*)dstb + ((size_t)(nt * KCH + chunk) * 2) * BLK + sel * BLK;
    #pragma unroll
    for (int j = 0; j < 8; j++) {
        uint32_t outv[4];
        #pragma unroll
        for (int kk = 0; kk < 4; kk++) {
            const int k2 = j * 8 + kk * 2;
            uint32_t hi, lo;
            split2(ws[k2][n], ws[k2 + 1][n], hi, lo);
            outv[kk] = sel ? lo : hi;
        }
        uint32_t bo = (uint32_t)(n * 128 + 16 * j);
        uint32_t sw = bo ^ ((bo >> 3) & 0x70);
        *(uint4*)(dst + sw) = make_uint4(outv[0], outv[1], outv[2], outv[3]);
    }
}

// -------- kv GEMM: fused epilogue -> g_kbf (RoPE) / g_vbf (transpose) -------
__global__ __launch_bounds__(256) void kv_mma_kernel(
    const float* __restrict__ cosb, const float* __restrict__ sinb)
{
    const uint32_t sb = smem_u32(dyn_smem);
    const int t = threadIdx.x, w = t >> 5, lane = t & 31;
    const int wm = w & 3, wn = w >> 2, g = lane >> 2, tig = lane & 3;
    const int bx = blockIdx.x, by = blockIdx.y;

    float acc[2][8][4];
    mma_tile_mainloop((const char*)g_A + (size_t)by * KCH * 2 * BLK,
                      (const char*)g_B + (size_t)bx * KCH * 2 * BLK, KCH, sb, acc);

    if (bx < 8) {
        // ---- K columns: RoPE in registers, write g_kbf swizzled hi/lo ----
        const int h = bx * 2 + wn;
        #pragma unroll
        for (int mi = 0; mi < 2; mi++) {
            const int row0 = by * 128 + wm * 32 + mi * 16 + g;
            const int b = row0 >> 12;
            #pragma unroll
            for (int qq = 0; qq < 2; qq++) {
                const int s = (row0 & 4095) + 8 * qq;
                char* dst = (char*)g_kbf +
                            ((size_t)((b * 16 + h) * 64 + (s >> 6))) * 16384;
                const int r = s & 63;
                const float2* cb  = (const float2*)&cosb[s * 32];
                const float2* sb2 = (const float2*)&sinb[s * 32];
                #pragma unroll
                for (int ni = 0; ni < 4; ni++) {
                    const int d0 = ni * 8 + tig * 2;   // 0..30, partner d0+32
                    const float k1a = acc[mi][ni][2 * qq];
                    const float k1b = acc[mi][ni][2 * qq + 1];
                    const float k2a = acc[mi][ni + 4][2 * qq];
                    const float k2b = acc[mi][ni + 4][2 * qq + 1];
                    const float2 c  = cb[d0 >> 1];
                    const float2 sn = sb2[d0 >> 1];
                    uint32_t hi, lo;
                    split2(k1a * c.x - k2a * sn.x, k1b * c.y - k2b * sn.y, hi, lo);
                    uint32_t bo = (uint32_t)(r * 128 + 2 * d0);
                    uint32_t sw = bo ^ ((bo >> 3) & 0x70);
                    *(uint32_t*)(dst + sw) = hi;
                    *(uint32_t*)(dst + 8192 + sw) = lo;
                    split2(k2a * c.x + k1a * sn.x, k2b * c.y + k1b * sn.y, hi, lo);
                    uint32_t bo2 = bo + 64;            // d0+32
                    uint32_t sw2 = bo2 ^ ((bo2 >> 3) & 0x70);
                    *(uint32_t*)(dst + sw2) = hi;
                    *(uint32_t*)(dst + 8192 + sw2) = lo;
                }
            }
        }
    } else {
        // ---- V columns: smem transpose (stage smem is free) -> g_vbf -------
        unsigned short* VH = (unsigned short*)(dyn_smem + OFF_STG);
        unsigned short* VL = VH + 128 * 136;   // 136-ushort pitch (272B = 17x16)
        #pragma unroll
        for (int mi = 0; mi < 2; mi++)
            #pragma unroll
            for (int ni = 0; ni < 8; ni++)
                #pragma unroll
                for (int q = 0; q < 4; q++) {
                    const int d = wn * 64 + ni * 8 + tig * 2 + (q & 1);
                    const int srow = wm * 32 + mi * 16 + g + 8 * (q >> 1);
                    const float v = acc[mi][ni][q];
                    const __nv_bfloat16 hb = __float2bfloat16(v);
                    const __nv_bfloat16 lb =
                        __float2bfloat16(v - __bfloat162float(hb));
                    VH[d * 136 + srow] = __bfloat16_as_ushort(hb);
                    VL[d * 136 + srow] = __bfloat16_as_ushort(lb);
                }
        __syncthreads();
        const int c = t & 127, sel = t >> 7;
        const int head = (bx - 8) * 2 + (c >> 6);
        const int dd = c & 63;
        const int b = by >> 5;
        const int scb = (by & 31) * 2;
        const unsigned short* src = (sel ? VL : VH) + c * 136;
        #pragma unroll
        for (int blk8 = 0; blk8 < 16; blk8++) {
            const uint4 v = *(const uint4*)(src + blk8 * 8);
            char* dst = (char*)g_vbf +
                        ((size_t)((b * 16 + head) * 64 + scb + (blk8 >> 3))) * 16384 +
                        sel * 8192;
            uint32_t bo = (uint32_t)(dd * 128 + 16 * (blk8 & 7));
            uint32_t sw = bo ^ ((bo >> 3) & 0x70);
            *(uint4*)(dst + sw) = v;
        }
    }
}

// -------- q GEMM: epilogue (x0.125 folded) -> g_qbf -------------------------
__global__ __launch_bounds__(256) void q_mma_kernel()
{
    const uint32_t sb = smem_u32(dyn_smem);
    const int t = threadIdx.x, w = t >> 5, lane = t & 31;
    const int wm = w & 3, wn = w >> 2, g = lane >> 2, tig = lane & 3;
    const int bx = blockIdx.x, by = blockIdx.y;   // bx 0..7, by 0..15

    float acc[2][8][4];
    mma_tile_mainloop((const char*)g_Aq + (size_t)by * KCH * 2 * BLK,
                      (const char*)g_Bq + (size_t)bx * KCH * 2 * BLK, KCH, sb, acc);

    const int h = bx * 2 + wn;
    #pragma unroll
    for (int mi = 0; mi < 2; mi++) {
        const int grow = by * 128 + wm * 32 + mi * 16 + g;
        const int b = grow >> 8, n = grow & 255;
        char* base = (char*)g_qbf + (size_t)(b * 16 + h) * 65536;
        #pragma unroll
        for (int ni = 0; ni < 8; ni++) {
            uint32_t hi, lo;
            split2(acc[mi][ni][0] * 0.125f, acc[mi][ni][1] * 0.125f, hi, lo);
            uint32_t bo = (uint32_t)(n * 128 + 16 * ni + 4 * tig);
            uint32_t sw = bo ^ ((bo >> 3) & 0x70);
            *(uint32_t*)(base + sw) = hi;
            *(uint32_t*)(base + 32768 + sw) = lo;
            split2(acc[mi][ni][2] * 0.125f, acc[mi][ni][3] * 0.125f, hi, lo);
            uint32_t bo2 = (uint32_t)((n + 8) * 128 + 16 * ni + 4 * tig);
            uint32_t sw2 = bo2 ^ ((bo2 >> 3) & 0x70);
            *(uint32_t*)(base + sw2) = hi;
            *(uint32_t*)(base + 32768 + sw2) = lo;
        }
    }
}

// -------- o GEMM: A = g_obf (attn out), epilogue -> out fp32 + bias ---------
__global__ __launch_bounds__(256) void o_mma_kernel(
    const float* __restrict__ bias, float* __restrict__ out)
{
    const uint32_t sb = smem_u32(dyn_smem);
    const int t = threadIdx.x, w = t >> 5, lane = t & 31;
    const int wm = w & 3, wn = w >> 2, g = lane >> 2, tig = lane & 3;
    const int bx = blockIdx.x, by = blockIdx.y;   // bx 0..7, by 0..15

    float acc[2][8][4];
    mma_tile_mainloop((const char*)g_obf + (size_t)by * KCH * 2 * BLK,
                      (const char*)g_Bo + (size_t)bx * KCH * 2 * BLK, KCH, sb, acc);

    #pragma unroll
    for (int mi = 0; mi < 2; mi++) {
        const int row0 = by * 128 + wm * 32 + mi * 16 + g;
        #pragma unroll
        for (int ni = 0; ni < 8; ni++) {
            const int col = bx * 128 + wn * 64 + ni * 8 + tig * 2;
            const float2 bb = *(const float2*)&bias[col];
            *(float2*)&out[(size_t)row0 * DIM + col] =
                make_float2(acc[mi][ni][0] + bb.x, acc[mi][ni][1] + bb.y);
            *(float2*)&out[(size_t)(row0 + 8) * DIM + col] =
                make_float2(acc[mi][ni][2] + bb.x, acc[mi][ni][3] + bb.y);
        }
    }
}

// -------- Flash attention, fixed-max softmax (clip guarantees max<=11) ------
#define ACH 32768      // per stage: K(hi|lo 16KB) + V(hi|lo 16KB)

__global__ __launch_bounds__(256) void attn_mma_kernel()
{
    const uint32_t sb = smem_u32(dyn_smem);
    const int t = threadIdx.x, w = t >> 5, lane = t & 31;
    const int bh = blockIdx.y;
    const int b = bh >> 4, h = bh & 15;
    const int n0 = blockIdx.x * 128;
    const int g = lane >> 2, tig = lane & 3;
    const int l15 = lane & 15;
    const uint32_t kb16 = (uint32_t)(lane & 16);
    const uint32_t mask = (uint32_t)((lane & 7) << 4);
    const uint32_t stg = sb + 64;

    if (t == 0) { mbar_init(sb, 1); mbar_init(sb + 8, 1); }
    __syncthreads();
    asm volatile("fence.proxy.async.shared::cta;" ::: "memory");

    const char* Qg = (const char*)g_qbf + (size_t)bh * 65536 + (size_t)n0 * 128;
    if (t == 0) {
        mbar_expect(sb, 32768);
        bulk_g2s(stg,         Qg,         16384, sb);
        bulk_g2s(stg + 16384, Qg + 32768, 16384, sb);
    }
    mbar_wait(sb, 0);

    uint32_t aqh[4][4], aql[4][4];
    #pragma unroll
    for (int ks = 0; ks < 4; ks++) {
        const uint32_t kx = ((uint32_t)(ks * 32) + kb16) ^ mask;
        const uint32_t ro = (uint32_t)((w * 16 + l15) * 128);
        ldmx4(aqh[ks], stg + ro + kx);
        ldmx4(aql[ks], stg + 16384 + ro + kx);
    }
    __syncthreads();

    const char* Kg = (const char*)g_kbf + (size_t)bh * 64 * 16384;
    const char* Vg = (const char*)g_vbf + (size_t)bh * 64 * 16384;
    if (t == 0) {
        #pragma unroll
        for (int c = 0; c < 2; c++) {
            mbar_expect(sb + 8 * c, 32768);
            bulk_g2s(stg + c * ACH,         Kg + (size_t)c * 16384, 16384, sb + 8 * c);
            bulk_g2s(stg + c * ACH + 16384, Vg + (size_t)c * 16384, 16384, sb + 8 * c);
        }
    }
    int ph0 = 1, ph1 = 0;

    // fixed max = 11 (logits clipped to [-11,11]): exp(s-11), plain accumulation
    float lA = 0.f, lB = 0.f;
    float o[8][4];
    #pragma unroll
    for (int ni = 0; ni < 8; ni++)
        #pragma unroll
        for (int q = 0; q < 4; q++) o[ni][q] = 0.f;

    for (int sc = 0; sc < 64; sc++) {
        const int s = sc & 1;
        if (s == 0) { mbar_wait(sb, ph0); ph0 ^= 1; }
        else        { mbar_wait(sb + 8, ph1); ph1 ^= 1; }
        const uint32_t kb = stg + s * ACH;
        const uint32_t vb = kb + 16384;

        float sacc[8][4];
        #pragma unroll
        for (int ni = 0; ni < 8; ni++)
            #pragma unroll
            for (int q = 0; q < 4; q++) sacc[ni][q] = 0.f;

        #pragma unroll
        for (int ks = 0; ks < 4; ks++) {
            const uint32_t kx = ((uint32_t)(ks * 32) + kb16) ^ mask;
            #pragma unroll
            for (int p = 0; p < 4; p++) {
                uint32_t kh[4], kl[4];
                const uint32_t ro = (uint32_t)((p * 16 + l15) * 128);
                ldmx4(kh, kb + ro + kx);
                ldmx4(kl, kb + 8192 + ro + kx);
                mma16816(sacc[2 * p + 0], aqh[ks], kh[0], kh[2]);
                mma16816(sacc[2 * p + 1], aqh[ks], kh[1], kh[3]);
                mma16816(sacc[2 * p + 0], aqh[ks], kl[0], kl[2]);
                mma16816(sacc[2 * p + 1], aqh[ks], kl[1], kl[3]);
                mma16816(sacc[2 * p + 0], aql[ks], kh[0], kh[2]);
                mma16816(sacc[2 * p + 1], aql[ks], kh[1], kh[3]);
            }
        }

        // p = exp(clip(s) - 11); accumulate row sums (no per-chunk reduction)
        #pragma unroll
        for (int ni = 0; ni < 8; ni++) {
            sacc[ni][0] = __expf(fminf(0.f, fmaxf(-22.f, sacc[ni][0] - 11.f)));
            sacc[ni][1] = __expf(fminf(0.f, fmaxf(-22.f, sacc[ni][1] - 11.f)));
            sacc[ni][2] = __expf(fminf(0.f, fmaxf(-22.f, sacc[ni][2] - 11.f)));
            sacc[ni][3] = __expf(fminf(0.f, fmaxf(-22.f, sacc[ni][3] - 11.f)));
            lA += sacc[ni][0] + sacc[ni][1];
            lB += sacc[ni][2] + sacc[ni][3];
        }

        // O += P V (3-pass; P fragments packed from sacc in A-operand order)
        #pragma unroll
        for (int ks = 0; ks < 4; ks++) {
            uint32_t pah[4], pal[4];
            split2(sacc[2 * ks][0],     sacc[2 * ks][1],     pah[0], pal[0]);
            split2(sacc[2 * ks][2],     sacc[2 * ks][3],     pah[1], pal[1]);
            split2(sacc[2 * ks + 1][0], sacc[2 * ks + 1][1], pah[2], pal[2]);
            split2(sacc[2 * ks + 1][2], sacc[2 * ks + 1][3], pah[3], pal[3]);
            const uint32_t kx = ((uint32_t)(ks * 32) + kb16) ^ mask;
            #pragma unroll
            for (int p = 0; p < 4; p++) {
                uint32_t vh[4], vl[4];
                const uint32_t ro = (uint32_t)((p * 16 + l15) * 128);
                ldmx4(vh, vb + ro + kx);
                ldmx4(vl, vb + 8192 + ro + kx);
                mma16816(o[2 * p + 0], pah, vh[0], vh[2]);
                mma16816(o[2 * p + 1], pah, vh[1], vh[3]);
                mma16816(o[2 * p + 0], pah, vl[0], vl[2]);
                mma16816(o[2 * p + 1], pah, vl[1], vl[3]);
                mma16816(o[2 * p + 0], pal, vh[0], vh[2]);
                mma16816(o[2 * p + 1], pal, vh[1], vh[3]);
            }
        }
        __syncthreads();
        if (t == 0 && sc + 2 < 64) {
            const int nc = sc + 2;
            const uint32_t dst = stg + s * ACH;
            mbar_expect(sb + 8 * s, 32768);
            bulk_g2s(dst,         Kg + (size_t)nc * 16384, 16384, sb + 8 * s);
            bulk_g2s(dst + 16384, Vg + (size_t)nc * 16384, 16384, sb + 8 * s);
        }
    }

    // finalize: quad-reduce row sums, normalize, write split-bf16 to g_obf
    lA += __shfl_xor_sync(0xffffffffu, lA, 1);
    lA += __shfl_xor_sync(0xffffffffu, lA, 2);
    lB += __shfl_xor_sync(0xffffffffu, lB, 1);
    lB += __shfl_xor_sync(0xffffffffu, lB, 2);
    const float iA = 1.f / lA, iB = 1.f / lB;
    const int growA = b * NLAT + n0 + w * 16 + g;
    const int mt = growA >> 7;
    char* ob = (char*)g_obf + ((size_t)(mt * KCH + h) * 2) * BLK;
    const int rA = growA & 127;
    #pragma unroll
    for (int ni = 0; ni < 8; ni++) {
        uint32_t hi, lo;
        split2(o[ni][0] * iA, o[ni][1] * iA, hi, lo);
        uint32_t bo = (uint32_t)(rA * 128 + 16 * ni + 4 * tig);
        uint32_t sw = bo ^ ((bo >> 3) & 0x70);
        *(uint32_t*)(ob + sw) = hi;
        *(uint32_t*)(ob + BLK + sw) = lo;
        split2(o[ni][2] * iB, o[ni][3] * iB, hi, lo);
        uint32_t bo2 = (uint32_t)((rA + 8) * 128 + 16 * ni + 4 * tig);
        uint32_t sw2 = bo2 ^ ((bo2 >> 3) & 0x70);
        *(uint32_t*)(ob + sw2) = hi;
        *(uint32_t*)(ob + BLK + sw2) = lo;
    }
}

// ---------------- host launcher --------------------------------------------
extern "C" void kernel_launch(void* const* d_in, const int* in_sizes, int n_in,
                              void* d_out, int out_size)
{
    const float* latents  = (const float*)d_in[0];
    const float* context  = (const float*)d_in[1];
    const float* cosb     = (const float*)d_in[2];
    const float* sinb     = (const float*)d_in[3];
    const float* ln_lat_g = (const float*)d_in[4];
    const float* ln_lat_b = (const float*)d_in[5];
    const float* ln_ctx_g = (const float*)d_in[6];
    const float* ln_ctx_b = (const float*)d_in[7];
    const float* Wq       = (const float*)d_in[8];
    const float* Wkv      = (const float*)d_in[9];
    const float* Wo       = (const float*)d_in[10];
    const float* bo       = (const float*)d_in[11];
    float* out = (float*)d_out;

    uint4 *pAq, *pA, *pBq, *pB, *pBo;
    cudaGetSymbolAddress((void**)&pAq, g_Aq);
    cudaGetSymbolAddress((void**)&pA,  g_A);
    cudaGetSymbolAddress((void**)&pBq, g_Bq);
    cudaGetSymbolAddress((void**)&pB,  g_B);
    cudaGetSymbolAddress((void**)&pBo, g_Bo);

    const int gemm_smem = OFF_STG + NSTG * STG_BYTES;   // 197632
    cudaFuncSetAttribute(kv_mma_kernel, cudaFuncAttributeMaxDynamicSharedMemorySize, gemm_smem);
    cudaFuncSetAttribute(q_mma_kernel,  cudaFuncAttributeMaxDynamicSharedMemorySize, gemm_smem);
    cudaFuncSetAttribute(o_mma_kernel,  cudaFuncAttributeMaxDynamicSharedMemorySize, gemm_smem);
    const int at_smem_bytes = 64 + 2 * ACH;   // 65600
    cudaFuncSetAttribute(attn_mma_kernel, cudaFuncAttributeMaxDynamicSharedMemorySize, at_smem_bytes);

    // 1. LayerNorms fused with split-bf16 A-prep (warp-per-row)
    ln_prep_kernel<<<(BATCH * NLAT) / 8, 256>>>(latents, ln_lat_g, ln_lat_b, pAq);
    ln_prep_kernel<<<(BATCH * SEQ)  / 8, 256>>>(context, ln_ctx_g, ln_ctx_b, pA);

    // 2. weight preps (smem-tiled, coalesced)
    wprep2_kernel<<<dim3(KCH, 8),  256>>>(Wq,  pBq, INNER);
    wprep2_kernel<<<dim3(KCH, 16), 256>>>(Wkv, pB,  GN);
    wprep2_kernel<<<dim3(KCH, 8),  256>>>(Wo,  pBo, DIM);

    // 3. q projection -> g_qbf (0.125 folded)
    q_mma_kernel<<<dim3(8, 16), 256, gemm_smem>>>();

    // 4. kv projection -> g_kbf (RoPE fused) / g_vbf (transpose fused)
    kv_mma_kernel<<<dim3(NT, MT), 256, gemm_smem>>>(cosb, sinb);

    // 5. attention -> g_obf (split-bf16 o-proj operand)
    attn_mma_kernel<<<dim3(NLAT / 128, BH), 256, at_smem_bytes>>>();

    // 6. output projection + bias -> out
    o_mma_kernel<<<dim3(8, 16), 256, gemm_smem>>>(bo, out);
}